// round 11
// baseline (speedup 1.0000x reference)
#include <cuda_runtime.h>
#include <cuda_fp16.h>
#include <math_constants.h>
#include <cstdint>

#define B_   2
#define T_   2048
#define D_   1024
#define H_   16
#define DK_  64
#define DM_  256
#define D2_  2048

// ---------------- scratch (device globals; no allocation allowed) ----------
// g_hcat, g_Q, g_K hold tf32 BITS; g_Vt holds fp16 TRANSPOSED [b][d][t];
// g_bias, g_O hold fp32.
__device__ float g_hcat[(size_t)B_ * T_ * D2_];
__device__ float g_Q   [(size_t)B_ * T_ * D_];
__device__ float g_K   [(size_t)B_ * T_ * D_];
__device__ __half g_Vt[(size_t)B_ * D_ * T_];
__device__ float g_bias[(size_t)B_ * T_ * T_];
__device__ float g_O   [(size_t)B_ * T_ * D_];

// ---------------- helpers ----------------------------------------------------
__device__ __forceinline__ uint32_t f2tf(float x) {
    uint32_t u; asm("cvt.rna.tf32.f32 %0, %1;" : "=r"(u) : "f"(x)); return u;
}
__device__ __forceinline__ uint32_t pack_f16(float lo, float hi) {
    uint32_t u; asm("cvt.rn.f16x2.f32 %0, %1, %2;" : "=r"(u) : "f"(hi), "f"(lo)); return u;
}
__device__ __forceinline__ void mma_tf32(float* c, const uint32_t* a, const uint32_t* b) {
    asm volatile("mma.sync.aligned.m16n8k8.row.col.f32.tf32.tf32.f32 "
        "{%0,%1,%2,%3}, {%4,%5,%6,%7}, {%8,%9}, {%0,%1,%2,%3};\n"
        : "+f"(c[0]), "+f"(c[1]), "+f"(c[2]), "+f"(c[3])
        : "r"(a[0]), "r"(a[1]), "r"(a[2]), "r"(a[3]), "r"(b[0]), "r"(b[1]));
}
__device__ __forceinline__ void mma_f16(float* c, const uint32_t* a, const uint32_t* b) {
    asm volatile("mma.sync.aligned.m16n8k16.row.col.f32.f16.f16.f32 "
        "{%0,%1,%2,%3}, {%4,%5,%6,%7}, {%8,%9}, {%0,%1,%2,%3};\n"
        : "+f"(c[0]), "+f"(c[1]), "+f"(c[2]), "+f"(c[3])
        : "r"(a[0]), "r"(a[1]), "r"(a[2]), "r"(a[3]), "r"(b[0]), "r"(b[1]));
}
__device__ __forceinline__ uint32_t smem_u32(const void* p) {
    uint32_t a;
    asm("{ .reg .u64 t; cvta.to.shared.u64 t, %1; cvt.u32.u64 %0, t; }" : "=r"(a) : "l"(p));
    return a;
}
__device__ __forceinline__ void cp_async16(uint32_t dst, const void* src) {
    asm volatile("cp.async.cg.shared.global [%0], [%1], 16;"
                 :: "r"(dst), "l"(src) : "memory");
}

// ---------------- hx transpose: Hx (B,D,T,1) -> g_hcat[:, 0:D] (tf32 bits) --
__global__ void transpose_hx_kernel(const float* __restrict__ Hx) {
    __shared__ float tile[32][33];
    int b  = blockIdx.z;
    int d0 = blockIdx.y * 32;
    int t0 = blockIdx.x * 32;
    #pragma unroll
    for (int yy = threadIdx.y; yy < 32; yy += 8)
        tile[yy][threadIdx.x] = Hx[((size_t)(b * D_ + d0 + yy)) * T_ + t0 + threadIdx.x];
    __syncthreads();
    #pragma unroll
    for (int yy = threadIdx.y; yy < 32; yy += 8)
        g_hcat[((size_t)(b * T_ + t0 + yy)) * D2_ + d0 + threadIdx.x] =
            __uint_as_float(f2tf(tile[threadIdx.x][yy]));
}

__global__ void copy_hf_kernel(const float4* __restrict__ Hf) {
    int idx = blockIdx.x * blockDim.x + threadIdx.x;
    if (idx >= B_ * T_ * (D_ / 4)) return;
    int row  = idx / (D_ / 4);
    int col4 = idx % (D_ / 4);
    float4 v = Hf[idx];
    float4 o = make_float4(__uint_as_float(f2tf(v.x)), __uint_as_float(f2tf(v.y)),
                           __uint_as_float(f2tf(v.z)), __uint_as_float(f2tf(v.w)));
    *reinterpret_cast<float4*>(&g_hcat[(size_t)row * D2_ + D_ + col4 * 4]) = o;
}

// ---------------- tf32 GEMM core (round-4 proven config) --------------------
// ATF32: A already holds tf32 bits.
// OUT: 0 = fp32 to C, 1 = tf32 bits to C, 2 = fp16 TRANSPOSED into g_Vt.
#define LDK   36
#define TILEW (128 * LDK)
#define GEMM_SMEM (2 * 2 * TILEW * 4)             // 73728 B

template <bool ATF32, int OUT>
__device__ __forceinline__ void gemm_core(
    const float* __restrict__ A, int lda,
    const float* __restrict__ W, int Kdim,
    const float* __restrict__ bias,
    float* __restrict__ C, int ldc,
    size_t mBase, int nBase, float* sm)
{
    const uint32_t sm_base = smem_u32(sm);
    const int tid  = threadIdx.x;
    const int lane = tid & 31;
    const int warp = tid >> 5;
    const int g    = lane >> 2;
    const int tq   = lane & 3;
    const int wm   = warp & 1;
    const int wn   = warp >> 1;

    const float* Ap = A + mBase * lda;
    const float* Wp = W + (size_t)nBase * Kdim;

    float acc[4][8][4];
    #pragma unroll
    for (int mt = 0; mt < 4; mt++)
        #pragma unroll
        for (int nt = 0; nt < 8; nt++)
            #pragma unroll
            for (int e = 0; e < 4; e++) acc[mt][nt][e] = 0.f;

    const int mrow = tid >> 3;
    const int kchk = (tid & 7) << 2;

    auto load_tile = [&](int s, int k0) {
        uint32_t dA = sm_base + (uint32_t)(s * 2 * TILEW) * 4;
        uint32_t dB = dA + TILEW * 4;
        #pragma unroll
        for (int j = 0; j < 8; j++) {
            int m = mrow + 16 * j;
            cp_async16(dA + (uint32_t)(m * LDK + kchk) * 4,
                       Ap + (size_t)m * lda + k0 + kchk);
            cp_async16(dB + (uint32_t)(m * LDK + kchk) * 4,
                       Wp + (size_t)m * Kdim + k0 + kchk);
        }
        asm volatile("cp.async.commit_group;" ::: "memory");
    };

    const int niter = Kdim >> 5;
    load_tile(0, 0);

    for (int it = 0; it < niter; it++) {
        if (it + 1 < niter) {
            load_tile((it + 1) & 1, (it + 1) << 5);
            asm volatile("cp.async.wait_group 1;" ::: "memory");
        } else {
            asm volatile("cp.async.wait_group 0;" ::: "memory");
        }
        __syncthreads();

        const float* sA = sm + (it & 1) * 2 * TILEW;
        const float* sB = sA + TILEW;
        const uint32_t* uA = reinterpret_cast<const uint32_t*>(sA);

        #pragma unroll
        for (int s = 0; s < 4; s++) {
            const int k = 8 * s;
            uint32_t af[4][4], bf[8][2];
            #pragma unroll
            for (int mt = 0; mt < 4; mt++) {
                int m0 = wm * 64 + mt * 16 + g;
                if (ATF32) {
                    af[mt][0] = uA[m0 * LDK + k + tq];
                    af[mt][1] = uA[(m0 + 8) * LDK + k + tq];
                    af[mt][2] = uA[m0 * LDK + k + tq + 4];
                    af[mt][3] = uA[(m0 + 8) * LDK + k + tq + 4];
                } else {
                    af[mt][0] = f2tf(sA[m0 * LDK + k + tq]);
                    af[mt][1] = f2tf(sA[(m0 + 8) * LDK + k + tq]);
                    af[mt][2] = f2tf(sA[m0 * LDK + k + tq + 4]);
                    af[mt][3] = f2tf(sA[(m0 + 8) * LDK + k + tq + 4]);
                }
            }
            #pragma unroll
            for (int nt = 0; nt < 8; nt++) {
                int n0 = wn * 64 + nt * 8 + g;
                bf[nt][0] = f2tf(sB[n0 * LDK + k + tq]);
                bf[nt][1] = f2tf(sB[n0 * LDK + k + tq + 4]);
            }
            #pragma unroll
            for (int mt = 0; mt < 4; mt++)
                #pragma unroll
                for (int nt = 0; nt < 8; nt++)
                    mma_tf32(acc[mt][nt], af[mt], bf[nt]);
        }
        __syncthreads();
    }

    #pragma unroll
    for (int nt = 0; nt < 8; nt++) {
        int col = nBase + wn * 64 + nt * 8 + 2 * tq;
        float2 bv = *reinterpret_cast<const float2*>(&bias[col]);
        #pragma unroll
        for (int mt = 0; mt < 4; mt++) {
            size_t row = mBase + wm * 64 + mt * 16 + g;
            float v00 = acc[mt][nt][0] + bv.x, v01 = acc[mt][nt][1] + bv.y;
            float v10 = acc[mt][nt][2] + bv.x, v11 = acc[mt][nt][3] + bv.y;
            if (OUT == 2) {
                // fp16 transposed: Vt[b][d][t], d = col, t = row % T
                int bb = (int)(row >> 11);
                int t  = (int)(row & 2047);
                __half* base = g_Vt + ((size_t)bb * D_ + col) * T_ + t;
                base[0]      = __float2half(v00);
                base[T_]     = __float2half(v01);
                base[8]      = __float2half(v10);
                base[T_ + 8] = __float2half(v11);
            } else if (OUT == 1) {
                *reinterpret_cast<float2*>(&C[row * ldc + col]) =
                    make_float2(__uint_as_float(f2tf(v00)), __uint_as_float(f2tf(v01)));
                *reinterpret_cast<float2*>(&C[(row + 8) * ldc + col]) =
                    make_float2(__uint_as_float(f2tf(v10)), __uint_as_float(f2tf(v11)));
            } else {
                *reinterpret_cast<float2*>(&C[row * ldc + col])       = make_float2(v00, v01);
                *reinterpret_cast<float2*>(&C[(row + 8) * ldc + col]) = make_float2(v10, v11);
            }
        }
    }
}

// ---- fused Q/K/V/bias projections: one launch, per-block routing -----------
__global__ void __launch_bounds__(128) proj_fused_kernel(
    const float* __restrict__ Gm,
    const float* __restrict__ Wq, const float* __restrict__ bq,
    const float* __restrict__ Wk, const float* __restrict__ bk,
    const float* __restrict__ Wv, const float* __restrict__ bv,
    const float* __restrict__ Wg, const float* __restrict__ bg)
{
    extern __shared__ float sm[];
    const int bx = blockIdx.x;
    const size_t mB = (size_t)blockIdx.y * 128;
    if (bx < 8)
        gemm_core<true, 1>(g_hcat, D2_, Wq, D2_, bq, g_Q,    D_, mB, bx * 128, sm);
    else if (bx < 16)
        gemm_core<true, 1>(g_hcat, D2_, Wk, D2_, bk, g_K,    D_, mB, (bx - 8) * 128, sm);
    else if (bx < 24)
        gemm_core<true, 2>(g_hcat, D2_, Wv, D_,  bv, nullptr, 0, mB, (bx - 16) * 128, sm);
    else
        gemm_core<false, 0>(Gm,    DM_, Wg, DM_, bg, g_bias, T_, mB, (bx - 24) * 128, sm);
}

// ---- plain GEMM (output projection; A fp32, out fp32) ----------------------
__global__ void __launch_bounds__(128) gemm_tf32_cp_kernel(
    const float* __restrict__ A, int lda,
    const float* __restrict__ W,
    const float* __restrict__ bias,
    float* __restrict__ C, int ldc, int Kdim)
{
    extern __shared__ float sm[];
    gemm_core<false, 0>(A, lda, W, Kdim, bias, C, ldc,
                        (size_t)blockIdx.y * 128, blockIdx.x * 128, sm);
}

// ---------------- flash attention: tf32 QK^T + fp16 PV ----------------------
#define ALDK 68
#define VLD  36                       // uint pitch for fp16 V^T (64 tok = 32 u + pad)
#define PLD  36                       // uint pitch for packed-fp16 P
#define KWU  (64 * ALDK)              // 4352 uints
#define VWU  (64 * VLD)               // 2304 uints
#define STGU (KWU + VWU)              // 6656 uints per stage
#define PWU  (128 * PLD)              // 4608 uints
#define ATTN_SMEM ((2 * STGU + PWU) * (int)sizeof(uint32_t))   // 71680 B

__global__ void __launch_bounds__(128) attn_tf32_kernel() {
    extern __shared__ uint32_t smu[];
    uint32_t* P = smu + 2 * STGU;     // packed-fp16 P, per-warp 32-row slabs

    const int tid  = threadIdx.x;
    const int lane = tid & 31;
    const int warp = tid >> 5;
    const int g    = lane >> 2;
    const int tq   = lane & 3;
    const int b    = blockIdx.z;
    const int h    = blockIdx.y;
    const int q0   = blockIdx.x * 128;

    const uint32_t smb = smem_u32(smu);

    const float* __restrict__ Qg = g_Q + (size_t)b * T_ * D_ + (size_t)h * DK_;
    const float* __restrict__ Kg = g_K + (size_t)b * T_ * D_ + (size_t)h * DK_;
    const __half* __restrict__ Vtg =
        g_Vt + ((size_t)b * D_ + (size_t)h * DK_) * T_;
    const float* __restrict__ Bg = g_bias + ((size_t)b * T_ + q0) * T_;

    // async loader: K tile (tf32 bits, [token][dk]) + V^T tile (fp16, [dk][token])
    auto load_kv = [&](int st, int k0) {
        uint32_t dK = smb + (uint32_t)(st * STGU) * 4;
        uint32_t dV = dK + KWU * 4;
        #pragma unroll
        for (int j = 0; j < 8; j++) {
            int i = tid + 128 * j;
            int r = i >> 4, c4 = (i & 15) << 2;
            cp_async16(dK + (uint32_t)(r * ALDK + c4) * 4,
                       Kg + (size_t)(k0 + r) * D_ + c4);
        }
        #pragma unroll
        for (int j = 0; j < 4; j++) {
            int i = tid + 128 * j;
            int r = i >> 3, c = i & 7;           // r = dk row, c = 16B chunk (8 tokens)
            cp_async16(dV + (uint32_t)(r * VLD + 4 * c) * 4,
                       Vtg + (size_t)r * T_ + k0 + 8 * c);
        }
        asm volatile("cp.async.commit_group;" ::: "memory");
    };

    load_kv(0, 0);

    // Q fragments loaded directly from gmem (tf32 bits; read once per CTA)
    uint32_t qa0[8][4], qa1[8][4];
    {
        const float* Q0 = Qg + (size_t)(q0 + warp * 32 + g) * D_;
        const float* Q1 = Q0 + 16 * D_;
        #pragma unroll
        for (int s = 0; s < 8; s++) {
            qa0[s][0] = __float_as_uint(Q0[8 * s + tq]);
            qa0[s][1] = __float_as_uint(Q0[8 * D_ + 8 * s + tq]);
            qa0[s][2] = __float_as_uint(Q0[8 * s + tq + 4]);
            qa0[s][3] = __float_as_uint(Q0[8 * D_ + 8 * s + tq + 4]);
            qa1[s][0] = __float_as_uint(Q1[8 * s + tq]);
            qa1[s][1] = __float_as_uint(Q1[8 * D_ + 8 * s + tq]);
            qa1[s][2] = __float_as_uint(Q1[8 * s + tq + 4]);
            qa1[s][3] = __float_as_uint(Q1[8 * D_ + 8 * s + tq + 4]);
        }
    }

    float o0[8][4], o1[8][4];
    #pragma unroll
    for (int nt = 0; nt < 8; nt++)
        #pragma unroll
        for (int e = 0; e < 4; e++) { o0[nt][e] = 0.f; o1[nt][e] = 0.f; }
    float rs[4] = {0.f, 0.f, 0.f, 0.f};

    uint32_t* Pw = P + warp * 32 * PLD;
    const int niter = T_ / 64;

    for (int it = 0; it < niter; it++) {
        const int k0 = it * 64;
        if (it + 1 < niter) {
            load_kv((it + 1) & 1, k0 + 64);
            asm volatile("cp.async.wait_group 1;" ::: "memory");
        } else {
            asm volatile("cp.async.wait_group 0;" ::: "memory");
        }
        __syncthreads();

        const uint32_t* sK  = smu + (it & 1) * STGU;
        const uint32_t* sVt = sK + KWU;
        const float*    B0  = Bg + (size_t)(warp * 32 + g) * T_ + k0;

        // S = Q K^T (tf32, two nt columns per pass), shift-free softmax, pack P
        #pragma unroll
        for (int ntp = 0; ntp < 4; ntp++) {
            const int ntA = 2 * ntp, ntB = 2 * ntp + 1;
            const int cbA = ntA * 8 + 2 * tq, cbB = ntB * 8 + 2 * tq;

            float2 bA00 = *reinterpret_cast<const float2*>(&B0[cbA]);
            float2 bA01 = *reinterpret_cast<const float2*>(&B0[8  * T_ + cbA]);
            float2 bA10 = *reinterpret_cast<const float2*>(&B0[16 * T_ + cbA]);
            float2 bA11 = *reinterpret_cast<const float2*>(&B0[24 * T_ + cbA]);
            float2 bB00 = *reinterpret_cast<const float2*>(&B0[cbB]);
            float2 bB01 = *reinterpret_cast<const float2*>(&B0[8  * T_ + cbB]);
            float2 bB10 = *reinterpret_cast<const float2*>(&B0[16 * T_ + cbB]);
            float2 bB11 = *reinterpret_cast<const float2*>(&B0[24 * T_ + cbB]);

            float sA0[4] = {0.f,0.f,0.f,0.f}, sA1[4] = {0.f,0.f,0.f,0.f};
            float sB0[4] = {0.f,0.f,0.f,0.f}, sB1[4] = {0.f,0.f,0.f,0.f};
            #pragma unroll
            for (int s = 0; s < 8; s++) {
                const uint32_t* KrA = sK + (ntA * 8 + g) * ALDK + 8 * s + tq;
                const uint32_t* KrB = sK + (ntB * 8 + g) * ALDK + 8 * s + tq;
                uint32_t bbA[2] = { KrA[0], KrA[4] };
                uint32_t bbB[2] = { KrB[0], KrB[4] };
                mma_tf32(sA0, qa0[s], bbA);
                mma_tf32(sA1, qa1[s], bbA);
                mma_tf32(sB0, qa0[s], bbB);
                mma_tf32(sB1, qa1[s], bbB);
            }

            float pA00 = __expf(fmaf(sA0[0], 0.125f, bA00.x));
            float pA01 = __expf(fmaf(sA0[1], 0.125f, bA00.y));
            float pA02 = __expf(fmaf(sA0[2], 0.125f, bA01.x));
            float pA03 = __expf(fmaf(sA0[3], 0.125f, bA01.y));
            float pA10 = __expf(fmaf(sA1[0], 0.125f, bA10.x));
            float pA11 = __expf(fmaf(sA1[1], 0.125f, bA10.y));
            float pA12 = __expf(fmaf(sA1[2], 0.125f, bA11.x));
            float pA13 = __expf(fmaf(sA1[3], 0.125f, bA11.y));
            float pB00 = __expf(fmaf(sB0[0], 0.125f, bB00.x));
            float pB01 = __expf(fmaf(sB0[1], 0.125f, bB00.y));
            float pB02 = __expf(fmaf(sB0[2], 0.125f, bB01.x));
            float pB03 = __expf(fmaf(sB0[3], 0.125f, bB01.y));
            float pB10 = __expf(fmaf(sB1[0], 0.125f, bB10.x));
            float pB11 = __expf(fmaf(sB1[1], 0.125f, bB10.y));
            float pB12 = __expf(fmaf(sB1[2], 0.125f, bB11.x));
            float pB13 = __expf(fmaf(sB1[3], 0.125f, bB11.y));

            rs[0] += pA00 + pA01 + pB00 + pB01;
            rs[1] += pA02 + pA03 + pB02 + pB03;
            rs[2] += pA10 + pA11 + pB10 + pB11;
            rs[3] += pA12 + pA13 + pB12 + pB13;

            // packed fp16 P: uint col = col/2 = nt*4 + tq
            Pw[g * PLD        + ntA * 4 + tq] = pack_f16(pA00, pA01);
            Pw[(g + 8) * PLD  + ntA * 4 + tq] = pack_f16(pA02, pA03);
            Pw[(g + 16) * PLD + ntA * 4 + tq] = pack_f16(pA10, pA11);
            Pw[(g + 24) * PLD + ntA * 4 + tq] = pack_f16(pA12, pA13);
            Pw[g * PLD        + ntB * 4 + tq] = pack_f16(pB00, pB01);
            Pw[(g + 8) * PLD  + ntB * 4 + tq] = pack_f16(pB02, pB03);
            Pw[(g + 16) * PLD + ntB * 4 + tq] = pack_f16(pB10, pB11);
            Pw[(g + 24) * PLD + ntB * 4 + tq] = pack_f16(pB12, pB13);
        }
        __syncwarp();

        // O += P V  (fp16 m16n8k16: 4 k-steps of 16 tokens)
        #pragma unroll
        for (int s = 0; s < 4; s++) {
            uint32_t pa0[4], pa1[4];
            pa0[0] = Pw[g * PLD + 8 * s + tq];
            pa0[1] = Pw[(g + 8) * PLD + 8 * s + tq];
            pa0[2] = Pw[g * PLD + 8 * s + tq + 4];
            pa0[3] = Pw[(g + 8) * PLD + 8 * s + tq + 4];
            pa1[0] = Pw[(g + 16) * PLD + 8 * s + tq];
            pa1[1] = Pw[(g + 24) * PLD + 8 * s + tq];
            pa1[2] = Pw[(g + 16) * PLD + 8 * s + tq + 4];
            pa1[3] = Pw[(g + 24) * PLD + 8 * s + tq + 4];
            #pragma unroll
            for (int nt = 0; nt < 8; nt++) {
                uint32_t bb[2];
                bb[0] = sVt[(nt * 8 + g) * VLD + 8 * s + tq];
                bb[1] = sVt[(nt * 8 + g) * VLD + 8 * s + tq + 4];
                mma_f16(o0[nt], pa0, bb);
                mma_f16(o1[nt], pa1, bb);
            }
        }
        __syncthreads();
    }

    #pragma unroll
    for (int e = 0; e < 4; e++) {
        rs[e] += __shfl_xor_sync(0xffffffffu, rs[e], 1);
        rs[e] += __shfl_xor_sync(0xffffffffu, rs[e], 2);
    }
    float inv0 = 1.0f / rs[0], inv1 = 1.0f / rs[1];
    float inv2 = 1.0f / rs[2], inv3 = 1.0f / rs[3];

    float* Og = g_O + (size_t)b * T_ * D_ + (size_t)h * DK_;
    size_t r0 = (size_t)q0 + warp * 32 + g;
    #pragma unroll
    for (int nt = 0; nt < 8; nt++) {
        int col = nt * 8 + 2 * tq;
        *reinterpret_cast<float2*>(&Og[r0 * D_ + col]) =
            make_float2(o0[nt][0] * inv0, o0[nt][1] * inv0);
        *reinterpret_cast<float2*>(&Og[(r0 + 8) * D_ + col]) =
            make_float2(o0[nt][2] * inv1, o0[nt][3] * inv1);
        *reinterpret_cast<float2*>(&Og[(r0 + 16) * D_ + col]) =
            make_float2(o1[nt][0] * inv2, o1[nt][1] * inv2);
        *reinterpret_cast<float2*>(&Og[(r0 + 24) * D_ + col]) =
            make_float2(o1[nt][2] * inv3, o1[nt][3] * inv3);
    }
}

// ---------------- launch ----------------------------------------------------
extern "C" void kernel_launch(void* const* d_in, const int* in_sizes, int n_in,
                              void* d_out, int out_size) {
    const float* Hx = (const float*)d_in[0];
    const float* Hf = (const float*)d_in[1];
    const float* Gm = (const float*)d_in[2];
    const float* Wg = (const float*)d_in[3];
    const float* bg = (const float*)d_in[4];
    const float* Wq = (const float*)d_in[5];
    const float* bq = (const float*)d_in[6];
    const float* Wk = (const float*)d_in[7];
    const float* bk = (const float*)d_in[8];
    const float* Wv = (const float*)d_in[9];
    const float* bv = (const float*)d_in[10];
    const float* Wo = (const float*)d_in[11];
    const float* bo = (const float*)d_in[12];
    float* out = (float*)d_out;

    float* O;
    cudaGetSymbolAddress((void**)&O, g_O);

    cudaFuncSetAttribute(proj_fused_kernel,
                         cudaFuncAttributeMaxDynamicSharedMemorySize, GEMM_SMEM);
    cudaFuncSetAttribute(gemm_tf32_cp_kernel,
                         cudaFuncAttributeMaxDynamicSharedMemorySize, GEMM_SMEM);
    cudaFuncSetAttribute(attn_tf32_kernel,
                         cudaFuncAttributeMaxDynamicSharedMemorySize, ATTN_SMEM);

    // 1) build hcat = [hx | Hf] (as tf32 bits)
    transpose_hx_kernel<<<dim3(T_ / 32, D_ / 32, B_), dim3(32, 8)>>>(Hx);
    copy_hf_kernel<<<(B_ * T_ * (D_ / 4) + 255) / 256, 256>>>((const float4*)Hf);

    // 2) all projections in ONE launch (Q/K tf32 bits, V -> fp16 transposed)
    proj_fused_kernel<<<dim3(40, 32), 128, GEMM_SMEM>>>(
        Gm, Wq, bq, Wk, bk, Wv, bv, Wg, bg);

    // 3) attention
    attn_tf32_kernel<<<dim3(T_ / 128, H_, B_), 128, ATTN_SMEM>>>();

    // 4) output projection (fp32 in/out)
    gemm_tf32_cp_kernel<<<dim3(D_ / 128, 32), 128, GEMM_SMEM>>>(O, D_, Wo, bo, out, D_, D_);
}

// round 12
// speedup vs baseline: 1.0093x; 1.0093x over previous
#include <cuda_runtime.h>
#include <cuda_fp16.h>
#include <math_constants.h>
#include <cstdint>

#define B_   2
#define T_   2048
#define D_   1024
#define H_   16
#define DK_  64
#define DM_  256
#define D2_  2048

// ---------------- scratch (device globals; no allocation allowed) ----------
// g_hcat, g_Q, g_K hold tf32 BITS; g_Vt holds fp16 TRANSPOSED [b][d][t];
// g_bias, g_O hold fp32.
__device__ float g_hcat[(size_t)B_ * T_ * D2_];
__device__ float g_Q   [(size_t)B_ * T_ * D_];
__device__ float g_K   [(size_t)B_ * T_ * D_];
__device__ __half g_Vt[(size_t)B_ * D_ * T_];
__device__ float g_bias[(size_t)B_ * T_ * T_];
__device__ float g_O   [(size_t)B_ * T_ * D_];

// ---------------- helpers ----------------------------------------------------
__device__ __forceinline__ uint32_t f2tf(float x) {
    uint32_t u; asm("cvt.rna.tf32.f32 %0, %1;" : "=r"(u) : "f"(x)); return u;
}
__device__ __forceinline__ uint32_t pack_f16(float lo, float hi) {
    uint32_t u; asm("cvt.rn.f16x2.f32 %0, %1, %2;" : "=r"(u) : "f"(hi), "f"(lo)); return u;
}
__device__ __forceinline__ void mma_tf32(float* c, const uint32_t* a, const uint32_t* b) {
    asm volatile("mma.sync.aligned.m16n8k8.row.col.f32.tf32.tf32.f32 "
        "{%0,%1,%2,%3}, {%4,%5,%6,%7}, {%8,%9}, {%0,%1,%2,%3};\n"
        : "+f"(c[0]), "+f"(c[1]), "+f"(c[2]), "+f"(c[3])
        : "r"(a[0]), "r"(a[1]), "r"(a[2]), "r"(a[3]), "r"(b[0]), "r"(b[1]));
}
__device__ __forceinline__ void mma_f16(float* c, const uint32_t* a, const uint32_t* b) {
    asm volatile("mma.sync.aligned.m16n8k16.row.col.f32.f16.f16.f32 "
        "{%0,%1,%2,%3}, {%4,%5,%6,%7}, {%8,%9}, {%0,%1,%2,%3};\n"
        : "+f"(c[0]), "+f"(c[1]), "+f"(c[2]), "+f"(c[3])
        : "r"(a[0]), "r"(a[1]), "r"(a[2]), "r"(a[3]), "r"(b[0]), "r"(b[1]));
}
__device__ __forceinline__ uint32_t smem_u32(const void* p) {
    uint32_t a;
    asm("{ .reg .u64 t; cvta.to.shared.u64 t, %1; cvt.u32.u64 %0, t; }" : "=r"(a) : "l"(p));
    return a;
}
__device__ __forceinline__ void cp_async16(uint32_t dst, const void* src) {
    asm volatile("cp.async.cg.shared.global [%0], [%1], 16;"
                 :: "r"(dst), "l"(src) : "memory");
}

// ---------------- hx transpose: Hx (B,D,T,1) -> g_hcat[:, 0:D] (tf32 bits) --
__global__ void transpose_hx_kernel(const float* __restrict__ Hx) {
    __shared__ float tile[32][33];
    int b  = blockIdx.z;
    int d0 = blockIdx.y * 32;
    int t0 = blockIdx.x * 32;
    #pragma unroll
    for (int yy = threadIdx.y; yy < 32; yy += 8)
        tile[yy][threadIdx.x] = Hx[((size_t)(b * D_ + d0 + yy)) * T_ + t0 + threadIdx.x];
    __syncthreads();
    #pragma unroll
    for (int yy = threadIdx.y; yy < 32; yy += 8)
        g_hcat[((size_t)(b * T_ + t0 + yy)) * D2_ + d0 + threadIdx.x] =
            __uint_as_float(f2tf(tile[threadIdx.x][yy]));
}

__global__ void copy_hf_kernel(const float4* __restrict__ Hf) {
    int idx = blockIdx.x * blockDim.x + threadIdx.x;
    if (idx >= B_ * T_ * (D_ / 4)) return;
    int row  = idx / (D_ / 4);
    int col4 = idx % (D_ / 4);
    float4 v = Hf[idx];
    float4 o = make_float4(__uint_as_float(f2tf(v.x)), __uint_as_float(f2tf(v.y)),
                           __uint_as_float(f2tf(v.z)), __uint_as_float(f2tf(v.w)));
    *reinterpret_cast<float4*>(&g_hcat[(size_t)row * D2_ + D_ + col4 * 4]) = o;
}

// ---------------- tf32 GEMM core (round-4 proven config) --------------------
// ATF32: A already holds tf32 bits.
// OUT: 0 = fp32 to C, 1 = tf32 bits to C, 2 = fp16 TRANSPOSED into g_Vt.
#define LDK   36
#define TILEW (128 * LDK)
#define GEMM_SMEM (2 * 2 * TILEW * 4)             // 73728 B

template <bool ATF32, int OUT>
__device__ __forceinline__ void gemm_core(
    const float* __restrict__ A, int lda,
    const float* __restrict__ W, int Kdim,
    const float* __restrict__ bias,
    float* __restrict__ C, int ldc,
    size_t mBase, int nBase, float* sm)
{
    const uint32_t sm_base = smem_u32(sm);
    const int tid  = threadIdx.x;
    const int lane = tid & 31;
    const int warp = tid >> 5;
    const int g    = lane >> 2;
    const int tq   = lane & 3;
    const int wm   = warp & 1;
    const int wn   = warp >> 1;

    const float* Ap = A + mBase * lda;
    const float* Wp = W + (size_t)nBase * Kdim;

    float acc[4][8][4];
    #pragma unroll
    for (int mt = 0; mt < 4; mt++)
        #pragma unroll
        for (int nt = 0; nt < 8; nt++)
            #pragma unroll
            for (int e = 0; e < 4; e++) acc[mt][nt][e] = 0.f;

    const int mrow = tid >> 3;
    const int kchk = (tid & 7) << 2;

    auto load_tile = [&](int s, int k0) {
        uint32_t dA = sm_base + (uint32_t)(s * 2 * TILEW) * 4;
        uint32_t dB = dA + TILEW * 4;
        #pragma unroll
        for (int j = 0; j < 8; j++) {
            int m = mrow + 16 * j;
            cp_async16(dA + (uint32_t)(m * LDK + kchk) * 4,
                       Ap + (size_t)m * lda + k0 + kchk);
            cp_async16(dB + (uint32_t)(m * LDK + kchk) * 4,
                       Wp + (size_t)m * Kdim + k0 + kchk);
        }
        asm volatile("cp.async.commit_group;" ::: "memory");
    };

    const int niter = Kdim >> 5;
    load_tile(0, 0);

    for (int it = 0; it < niter; it++) {
        if (it + 1 < niter) {
            load_tile((it + 1) & 1, (it + 1) << 5);
            asm volatile("cp.async.wait_group 1;" ::: "memory");
        } else {
            asm volatile("cp.async.wait_group 0;" ::: "memory");
        }
        __syncthreads();

        const float* sA = sm + (it & 1) * 2 * TILEW;
        const float* sB = sA + TILEW;
        const uint32_t* uA = reinterpret_cast<const uint32_t*>(sA);

        #pragma unroll
        for (int s = 0; s < 4; s++) {
            const int k = 8 * s;
            uint32_t af[4][4], bf[8][2];
            #pragma unroll
            for (int mt = 0; mt < 4; mt++) {
                int m0 = wm * 64 + mt * 16 + g;
                if (ATF32) {
                    af[mt][0] = uA[m0 * LDK + k + tq];
                    af[mt][1] = uA[(m0 + 8) * LDK + k + tq];
                    af[mt][2] = uA[m0 * LDK + k + tq + 4];
                    af[mt][3] = uA[(m0 + 8) * LDK + k + tq + 4];
                } else {
                    af[mt][0] = f2tf(sA[m0 * LDK + k + tq]);
                    af[mt][1] = f2tf(sA[(m0 + 8) * LDK + k + tq]);
                    af[mt][2] = f2tf(sA[m0 * LDK + k + tq + 4]);
                    af[mt][3] = f2tf(sA[(m0 + 8) * LDK + k + tq + 4]);
                }
            }
            #pragma unroll
            for (int nt = 0; nt < 8; nt++) {
                int n0 = wn * 64 + nt * 8 + g;
                bf[nt][0] = f2tf(sB[n0 * LDK + k + tq]);
                bf[nt][1] = f2tf(sB[n0 * LDK + k + tq + 4]);
            }
            #pragma unroll
            for (int mt = 0; mt < 4; mt++)
                #pragma unroll
                for (int nt = 0; nt < 8; nt++)
                    mma_tf32(acc[mt][nt], af[mt], bf[nt]);
        }
        __syncthreads();
    }

    #pragma unroll
    for (int nt = 0; nt < 8; nt++) {
        int col = nBase + wn * 64 + nt * 8 + 2 * tq;
        float2 bv = *reinterpret_cast<const float2*>(&bias[col]);
        #pragma unroll
        for (int mt = 0; mt < 4; mt++) {
            size_t row = mBase + wm * 64 + mt * 16 + g;
            float v00 = acc[mt][nt][0] + bv.x, v01 = acc[mt][nt][1] + bv.y;
            float v10 = acc[mt][nt][2] + bv.x, v11 = acc[mt][nt][3] + bv.y;
            if (OUT == 2) {
                // fp16 transposed: Vt[b][d][t], d = col, t = row % T
                int bb = (int)(row >> 11);
                int t  = (int)(row & 2047);
                __half* base = g_Vt + ((size_t)bb * D_ + col) * T_ + t;
                base[0]      = __float2half(v00);
                base[T_]     = __float2half(v01);
                base[8]      = __float2half(v10);
                base[T_ + 8] = __float2half(v11);
            } else if (OUT == 1) {
                *reinterpret_cast<float2*>(&C[row * ldc + col]) =
                    make_float2(__uint_as_float(f2tf(v00)), __uint_as_float(f2tf(v01)));
                *reinterpret_cast<float2*>(&C[(row + 8) * ldc + col]) =
                    make_float2(__uint_as_float(f2tf(v10)), __uint_as_float(f2tf(v11)));
            } else {
                *reinterpret_cast<float2*>(&C[row * ldc + col])       = make_float2(v00, v01);
                *reinterpret_cast<float2*>(&C[(row + 8) * ldc + col]) = make_float2(v10, v11);
            }
        }
    }
}

// ---- fused Q/K/V/bias projections: one launch, per-block routing -----------
__global__ void __launch_bounds__(128) proj_fused_kernel(
    const float* __restrict__ Gm,
    const float* __restrict__ Wq, const float* __restrict__ bq,
    const float* __restrict__ Wk, const float* __restrict__ bk,
    const float* __restrict__ Wv, const float* __restrict__ bv,
    const float* __restrict__ Wg, const float* __restrict__ bg)
{
    extern __shared__ float sm[];
    const int bx = blockIdx.x;
    const size_t mB = (size_t)blockIdx.y * 128;
    if (bx < 8)
        gemm_core<true, 1>(g_hcat, D2_, Wq, D2_, bq, g_Q,    D_, mB, bx * 128, sm);
    else if (bx < 16)
        gemm_core<true, 1>(g_hcat, D2_, Wk, D2_, bk, g_K,    D_, mB, (bx - 8) * 128, sm);
    else if (bx < 24)
        gemm_core<true, 2>(g_hcat, D2_, Wv, D_,  bv, nullptr, 0, mB, (bx - 16) * 128, sm);
    else
        gemm_core<false, 0>(Gm,    DM_, Wg, DM_, bg, g_bias, T_, mB, (bx - 24) * 128, sm);
}

// ---- plain GEMM (output projection; A fp32, out fp32) ----------------------
__global__ void __launch_bounds__(128) gemm_tf32_cp_kernel(
    const float* __restrict__ A, int lda,
    const float* __restrict__ W,
    const float* __restrict__ bias,
    float* __restrict__ C, int ldc, int Kdim)
{
    extern __shared__ float sm[];
    gemm_core<false, 0>(A, lda, W, Kdim, bias, C, ldc,
                        (size_t)blockIdx.y * 128, blockIdx.x * 128, sm);
}

// ---------------- flash attention: tf32 QK^T + fp16 PV, smem-staged Q -------
// Q is staged into the P region and overwritten by P each iteration, which
// FORCES the Q fragments to stay register-resident (no LDG rematerialization).
#define ALDK 68
#define VLD  36                       // uint pitch for fp16 V^T (64 tok = 32 u + pad)
#define PLD  68                       // uint pitch for Q-stage / packed-fp16 P
#define KWU  (64 * ALDK)              // 4352 uints
#define VWU  (64 * VLD)               // 2304 uints
#define STGU (KWU + VWU)              // 6656 uints per stage
#define PQW  (128 * PLD)              // 8704 uints (Q stage, then P)
#define ATTN_SMEM ((2 * STGU + PQW) * (int)sizeof(uint32_t))   // 88064 B

__global__ void __launch_bounds__(128) attn_tf32_kernel() {
    extern __shared__ uint32_t smu[];
    uint32_t* P = smu + 2 * STGU;     // Q staging, then per-warp P slabs

    const int tid  = threadIdx.x;
    const int lane = tid & 31;
    const int warp = tid >> 5;
    const int g    = lane >> 2;
    const int tq   = lane & 3;
    const int b    = blockIdx.z;
    const int h    = blockIdx.y;
    const int q0   = blockIdx.x * 128;

    const uint32_t smb = smem_u32(smu);

    const float* __restrict__ Qg = g_Q + (size_t)b * T_ * D_ + (size_t)h * DK_;
    const float* __restrict__ Kg = g_K + (size_t)b * T_ * D_ + (size_t)h * DK_;
    const __half* __restrict__ Vtg =
        g_Vt + ((size_t)b * D_ + (size_t)h * DK_) * T_;
    const float* __restrict__ Bg = g_bias + ((size_t)b * T_ + q0) * T_;

    // async loader: K tile (tf32 bits, [token][dk]) + V^T tile (fp16, [dk][token])
    auto load_kv = [&](int st, int k0) {
        uint32_t dK = smb + (uint32_t)(st * STGU) * 4;
        uint32_t dV = dK + KWU * 4;
        #pragma unroll
        for (int j = 0; j < 8; j++) {
            int i = tid + 128 * j;
            int r = i >> 4, c4 = (i & 15) << 2;
            cp_async16(dK + (uint32_t)(r * ALDK + c4) * 4,
                       Kg + (size_t)(k0 + r) * D_ + c4);
        }
        #pragma unroll
        for (int j = 0; j < 4; j++) {
            int i = tid + 128 * j;
            int r = i >> 3, c = i & 7;           // r = dk row, c = 16B chunk (8 tokens)
            cp_async16(dV + (uint32_t)(r * VLD + 4 * c) * 4,
                       Vtg + (size_t)r * T_ + k0 + 8 * c);
        }
        asm volatile("cp.async.commit_group;" ::: "memory");
    };

    load_kv(0, 0);

    // stage Q (128 x 64 tf32 bits) into the P region (coalesced uint4)
    #pragma unroll
    for (int i = tid; i < 128 * 16; i += 128) {
        int r = i >> 4, c4 = (i & 15) << 2;
        uint4 v = *reinterpret_cast<const uint4*>(&Qg[(size_t)(q0 + r) * D_ + c4]);
        *reinterpret_cast<uint4*>(&P[r * PLD + c4]) = v;
    }
    __syncthreads();

    // Q fragments -> registers (smem source is clobbered by P below, so these
    // MUST stay register-resident)
    uint32_t qa0[8][4], qa1[8][4];
    {
        const uint32_t* Q0 = P + (warp * 32 + g) * PLD;
        const uint32_t* Q1 = P + (warp * 32 + 16 + g) * PLD;
        #pragma unroll
        for (int s = 0; s < 8; s++) {
            qa0[s][0] = Q0[8 * s + tq];
            qa0[s][1] = Q0[8 * PLD + 8 * s + tq];
            qa0[s][2] = Q0[8 * s + tq + 4];
            qa0[s][3] = Q0[8 * PLD + 8 * s + tq + 4];
            qa1[s][0] = Q1[8 * s + tq];
            qa1[s][1] = Q1[8 * PLD + 8 * s + tq];
            qa1[s][2] = Q1[8 * s + tq + 4];
            qa1[s][3] = Q1[8 * PLD + 8 * s + tq + 4];
        }
    }
    __syncthreads();

    float o0[8][4], o1[8][4];
    #pragma unroll
    for (int nt = 0; nt < 8; nt++)
        #pragma unroll
        for (int e = 0; e < 4; e++) { o0[nt][e] = 0.f; o1[nt][e] = 0.f; }
    float rs[4] = {0.f, 0.f, 0.f, 0.f};

    uint32_t* Pw = P + warp * 32 * PLD;
    const int niter = T_ / 64;

    for (int it = 0; it < niter; it++) {
        const int k0 = it * 64;
        if (it + 1 < niter) {
            load_kv((it + 1) & 1, k0 + 64);
            asm volatile("cp.async.wait_group 1;" ::: "memory");
        } else {
            asm volatile("cp.async.wait_group 0;" ::: "memory");
        }
        __syncthreads();

        const uint32_t* sK  = smu + (it & 1) * STGU;
        const uint32_t* sVt = sK + KWU;
        const float*    B0  = Bg + (size_t)(warp * 32 + g) * T_ + k0;

        // S = Q K^T (tf32, two nt columns per pass), shift-free softmax, pack P
        #pragma unroll
        for (int ntp = 0; ntp < 4; ntp++) {
            const int ntA = 2 * ntp, ntB = 2 * ntp + 1;
            const int cbA = ntA * 8 + 2 * tq, cbB = ntB * 8 + 2 * tq;

            float2 bA00 = *reinterpret_cast<const float2*>(&B0[cbA]);
            float2 bA01 = *reinterpret_cast<const float2*>(&B0[8  * T_ + cbA]);
            float2 bA10 = *reinterpret_cast<const float2*>(&B0[16 * T_ + cbA]);
            float2 bA11 = *reinterpret_cast<const float2*>(&B0[24 * T_ + cbA]);
            float2 bB00 = *reinterpret_cast<const float2*>(&B0[cbB]);
            float2 bB01 = *reinterpret_cast<const float2*>(&B0[8  * T_ + cbB]);
            float2 bB10 = *reinterpret_cast<const float2*>(&B0[16 * T_ + cbB]);
            float2 bB11 = *reinterpret_cast<const float2*>(&B0[24 * T_ + cbB]);

            float sA0[4] = {0.f,0.f,0.f,0.f}, sA1[4] = {0.f,0.f,0.f,0.f};
            float sB0[4] = {0.f,0.f,0.f,0.f}, sB1[4] = {0.f,0.f,0.f,0.f};
            #pragma unroll
            for (int s = 0; s < 8; s++) {
                const uint32_t* KrA = sK + (ntA * 8 + g) * ALDK + 8 * s + tq;
                const uint32_t* KrB = sK + (ntB * 8 + g) * ALDK + 8 * s + tq;
                uint32_t bbA[2] = { KrA[0], KrA[4] };
                uint32_t bbB[2] = { KrB[0], KrB[4] };
                mma_tf32(sA0, qa0[s], bbA);
                mma_tf32(sA1, qa1[s], bbA);
                mma_tf32(sB0, qa0[s], bbB);
                mma_tf32(sB1, qa1[s], bbB);
            }

            float pA00 = __expf(fmaf(sA0[0], 0.125f, bA00.x));
            float pA01 = __expf(fmaf(sA0[1], 0.125f, bA00.y));
            float pA02 = __expf(fmaf(sA0[2], 0.125f, bA01.x));
            float pA03 = __expf(fmaf(sA0[3], 0.125f, bA01.y));
            float pA10 = __expf(fmaf(sA1[0], 0.125f, bA10.x));
            float pA11 = __expf(fmaf(sA1[1], 0.125f, bA10.y));
            float pA12 = __expf(fmaf(sA1[2], 0.125f, bA11.x));
            float pA13 = __expf(fmaf(sA1[3], 0.125f, bA11.y));
            float pB00 = __expf(fmaf(sB0[0], 0.125f, bB00.x));
            float pB01 = __expf(fmaf(sB0[1], 0.125f, bB00.y));
            float pB02 = __expf(fmaf(sB0[2], 0.125f, bB01.x));
            float pB03 = __expf(fmaf(sB0[3], 0.125f, bB01.y));
            float pB10 = __expf(fmaf(sB1[0], 0.125f, bB10.x));
            float pB11 = __expf(fmaf(sB1[1], 0.125f, bB10.y));
            float pB12 = __expf(fmaf(sB1[2], 0.125f, bB11.x));
            float pB13 = __expf(fmaf(sB1[3], 0.125f, bB11.y));

            rs[0] += pA00 + pA01 + pB00 + pB01;
            rs[1] += pA02 + pA03 + pB02 + pB03;
            rs[2] += pA10 + pA11 + pB10 + pB11;
            rs[3] += pA12 + pA13 + pB12 + pB13;

            // packed fp16 P: uint col = col/2 = nt*4 + tq
            Pw[g * PLD        + ntA * 4 + tq] = pack_f16(pA00, pA01);
            Pw[(g + 8) * PLD  + ntA * 4 + tq] = pack_f16(pA02, pA03);
            Pw[(g + 16) * PLD + ntA * 4 + tq] = pack_f16(pA10, pA11);
            Pw[(g + 24) * PLD + ntA * 4 + tq] = pack_f16(pA12, pA13);
            Pw[g * PLD        + ntB * 4 + tq] = pack_f16(pB00, pB01);
            Pw[(g + 8) * PLD  + ntB * 4 + tq] = pack_f16(pB02, pB03);
            Pw[(g + 16) * PLD + ntB * 4 + tq] = pack_f16(pB10, pB11);
            Pw[(g + 24) * PLD + ntB * 4 + tq] = pack_f16(pB12, pB13);
        }
        __syncwarp();

        // O += P V  (fp16 m16n8k16: 4 k-steps of 16 tokens)
        #pragma unroll
        for (int s = 0; s < 4; s++) {
            uint32_t pa0[4], pa1[4];
            pa0[0] = Pw[g * PLD + 8 * s + tq];
            pa0[1] = Pw[(g + 8) * PLD + 8 * s + tq];
            pa0[2] = Pw[g * PLD + 8 * s + tq + 4];
            pa0[3] = Pw[(g + 8) * PLD + 8 * s + tq + 4];
            pa1[0] = Pw[(g + 16) * PLD + 8 * s + tq];
            pa1[1] = Pw[(g + 24) * PLD + 8 * s + tq];
            pa1[2] = Pw[(g + 16) * PLD + 8 * s + tq + 4];
            pa1[3] = Pw[(g + 24) * PLD + 8 * s + tq + 4];
            #pragma unroll
            for (int nt = 0; nt < 8; nt++) {
                uint32_t bb[2];
                bb[0] = sVt[(nt * 8 + g) * VLD + 8 * s + tq];
                bb[1] = sVt[(nt * 8 + g) * VLD + 8 * s + tq + 4];
                mma_f16(o0[nt], pa0, bb);
                mma_f16(o1[nt], pa1, bb);
            }
        }
        __syncthreads();
    }

    #pragma unroll
    for (int e = 0; e < 4; e++) {
        rs[e] += __shfl_xor_sync(0xffffffffu, rs[e], 1);
        rs[e] += __shfl_xor_sync(0xffffffffu, rs[e], 2);
    }
    float inv0 = 1.0f / rs[0], inv1 = 1.0f / rs[1];
    float inv2 = 1.0f / rs[2], inv3 = 1.0f / rs[3];

    float* Og = g_O + (size_t)b * T_ * D_ + (size_t)h * DK_;
    size_t r0 = (size_t)q0 + warp * 32 + g;
    #pragma unroll
    for (int nt = 0; nt < 8; nt++) {
        int col = nt * 8 + 2 * tq;
        *reinterpret_cast<float2*>(&Og[r0 * D_ + col]) =
            make_float2(o0[nt][0] * inv0, o0[nt][1] * inv0);
        *reinterpret_cast<float2*>(&Og[(r0 + 8) * D_ + col]) =
            make_float2(o0[nt][2] * inv1, o0[nt][3] * inv1);
        *reinterpret_cast<float2*>(&Og[(r0 + 16) * D_ + col]) =
            make_float2(o1[nt][0] * inv2, o1[nt][1] * inv2);
        *reinterpret_cast<float2*>(&Og[(r0 + 24) * D_ + col]) =
            make_float2(o1[nt][2] * inv3, o1[nt][3] * inv3);
    }
}

// ---------------- launch ----------------------------------------------------
extern "C" void kernel_launch(void* const* d_in, const int* in_sizes, int n_in,
                              void* d_out, int out_size) {
    const float* Hx = (const float*)d_in[0];
    const float* Hf = (const float*)d_in[1];
    const float* Gm = (const float*)d_in[2];
    const float* Wg = (const float*)d_in[3];
    const float* bg = (const float*)d_in[4];
    const float* Wq = (const float*)d_in[5];
    const float* bq = (const float*)d_in[6];
    const float* Wk = (const float*)d_in[7];
    const float* bk = (const float*)d_in[8];
    const float* Wv = (const float*)d_in[9];
    const float* bv = (const float*)d_in[10];
    const float* Wo = (const float*)d_in[11];
    const float* bo = (const float*)d_in[12];
    float* out = (float*)d_out;

    float* O;
    cudaGetSymbolAddress((void**)&O, g_O);

    cudaFuncSetAttribute(proj_fused_kernel,
                         cudaFuncAttributeMaxDynamicSharedMemorySize, GEMM_SMEM);
    cudaFuncSetAttribute(gemm_tf32_cp_kernel,
                         cudaFuncAttributeMaxDynamicSharedMemorySize, GEMM_SMEM);
    cudaFuncSetAttribute(attn_tf32_kernel,
                         cudaFuncAttributeMaxDynamicSharedMemorySize, ATTN_SMEM);

    // 1) build hcat = [hx | Hf] (as tf32 bits)
    transpose_hx_kernel<<<dim3(T_ / 32, D_ / 32, B_), dim3(32, 8)>>>(Hx);
    copy_hf_kernel<<<(B_ * T_ * (D_ / 4) + 255) / 256, 256>>>((const float4*)Hf);

    // 2) all projections in ONE launch (Q/K tf32 bits, V -> fp16 transposed)
    proj_fused_kernel<<<dim3(40, 32), 128, GEMM_SMEM>>>(
        Gm, Wq, bq, Wk, bk, Wv, bv, Wg, bg);

    // 3) attention
    attn_tf32_kernel<<<dim3(T_ / 128, H_, B_), 128, ATTN_SMEM>>>();

    // 4) output projection (fp32 in/out)
    gemm_tf32_cp_kernel<<<dim3(D_ / 128, 32), 128, GEMM_SMEM>>>(O, D_, Wo, bo, out, D_, D_);
}

// round 13
// speedup vs baseline: 1.3634x; 1.3509x over previous
#include <cuda_runtime.h>
#include <cuda_fp16.h>
#include <math_constants.h>
#include <cstdint>

#define B_   2
#define T_   2048
#define D_   1024
#define H_   16
#define DK_  64
#define DM_  256
#define D2_  2048

// ---------------- scratch (device globals; no allocation allowed) ----------
// g_hcat, g_Q, g_K hold tf32 BITS; g_Vt holds fp16 TRANSPOSED [b][d][t];
// g_bias, g_O hold fp32.
__device__ float g_hcat[(size_t)B_ * T_ * D2_];
__device__ float g_Q   [(size_t)B_ * T_ * D_];
__device__ float g_K   [(size_t)B_ * T_ * D_];
__device__ __half g_Vt[(size_t)B_ * D_ * T_];
__device__ float g_bias[(size_t)B_ * T_ * T_];
__device__ float g_O   [(size_t)B_ * T_ * D_];

// ---------------- helpers ----------------------------------------------------
__device__ __forceinline__ uint32_t f2tf(float x) {
    uint32_t u; asm("cvt.rna.tf32.f32 %0, %1;" : "=r"(u) : "f"(x)); return u;
}
__device__ __forceinline__ uint32_t pack_f16(float lo, float hi) {
    uint32_t u; asm("cvt.rn.f16x2.f32 %0, %1, %2;" : "=r"(u) : "f"(hi), "f"(lo)); return u;
}
__device__ __forceinline__ void mma_tf32(float* c, const uint32_t* a, const uint32_t* b) {
    asm volatile("mma.sync.aligned.m16n8k8.row.col.f32.tf32.tf32.f32 "
        "{%0,%1,%2,%3}, {%4,%5,%6,%7}, {%8,%9}, {%0,%1,%2,%3};\n"
        : "+f"(c[0]), "+f"(c[1]), "+f"(c[2]), "+f"(c[3])
        : "r"(a[0]), "r"(a[1]), "r"(a[2]), "r"(a[3]), "r"(b[0]), "r"(b[1]));
}
__device__ __forceinline__ void mma_f16(float* c, const uint32_t* a, const uint32_t* b) {
    asm volatile("mma.sync.aligned.m16n8k16.row.col.f32.f16.f16.f32 "
        "{%0,%1,%2,%3}, {%4,%5,%6,%7}, {%8,%9}, {%0,%1,%2,%3};\n"
        : "+f"(c[0]), "+f"(c[1]), "+f"(c[2]), "+f"(c[3])
        : "r"(a[0]), "r"(a[1]), "r"(a[2]), "r"(a[3]), "r"(b[0]), "r"(b[1]));
}
__device__ __forceinline__ uint32_t smem_u32(const void* p) {
    uint32_t a;
    asm("{ .reg .u64 t; cvta.to.shared.u64 t, %1; cvt.u32.u64 %0, t; }" : "=r"(a) : "l"(p));
    return a;
}
__device__ __forceinline__ void cp_async16(uint32_t dst, const void* src) {
    asm volatile("cp.async.cg.shared.global [%0], [%1], 16;"
                 :: "r"(dst), "l"(src) : "memory");
}

// ---------------- hx transpose: Hx (B,D,T,1) -> g_hcat[:, 0:D] (tf32 bits) --
__global__ void transpose_hx_kernel(const float* __restrict__ Hx) {
    __shared__ float tile[32][33];
    int b  = blockIdx.z;
    int d0 = blockIdx.y * 32;
    int t0 = blockIdx.x * 32;
    #pragma unroll
    for (int yy = threadIdx.y; yy < 32; yy += 8)
        tile[yy][threadIdx.x] = Hx[((size_t)(b * D_ + d0 + yy)) * T_ + t0 + threadIdx.x];
    __syncthreads();
    #pragma unroll
    for (int yy = threadIdx.y; yy < 32; yy += 8)
        g_hcat[((size_t)(b * T_ + t0 + yy)) * D2_ + d0 + threadIdx.x] =
            __uint_as_float(f2tf(tile[threadIdx.x][yy]));
}

__global__ void copy_hf_kernel(const float4* __restrict__ Hf) {
    int idx = blockIdx.x * blockDim.x + threadIdx.x;
    if (idx >= B_ * T_ * (D_ / 4)) return;
    int row  = idx / (D_ / 4);
    int col4 = idx % (D_ / 4);
    float4 v = Hf[idx];
    float4 o = make_float4(__uint_as_float(f2tf(v.x)), __uint_as_float(f2tf(v.y)),
                           __uint_as_float(f2tf(v.z)), __uint_as_float(f2tf(v.w)));
    *reinterpret_cast<float4*>(&g_hcat[(size_t)row * D2_ + D_ + col4 * 4]) = o;
}

// ---------------- tf32 GEMM core (round-4 proven config) --------------------
// ATF32: A already holds tf32 bits.
// OUT: 0 = fp32 to C, 1 = tf32 bits to C, 2 = fp16 TRANSPOSED into g_Vt.
#define LDK   36
#define TILEW (128 * LDK)
#define GEMM_SMEM (2 * 2 * TILEW * 4)             // 73728 B

template <bool ATF32, int OUT>
__device__ __forceinline__ void gemm_core(
    const float* __restrict__ A, int lda,
    const float* __restrict__ W, int Kdim,
    const float* __restrict__ bias,
    float* __restrict__ C, int ldc,
    size_t mBase, int nBase, float* sm)
{
    const uint32_t sm_base = smem_u32(sm);
    const int tid  = threadIdx.x;
    const int lane = tid & 31;
    const int warp = tid >> 5;
    const int g    = lane >> 2;
    const int tq   = lane & 3;
    const int wm   = warp & 1;
    const int wn   = warp >> 1;

    const float* Ap = A + mBase * lda;
    const float* Wp = W + (size_t)nBase * Kdim;

    float acc[4][8][4];
    #pragma unroll
    for (int mt = 0; mt < 4; mt++)
        #pragma unroll
        for (int nt = 0; nt < 8; nt++)
            #pragma unroll
            for (int e = 0; e < 4; e++) acc[mt][nt][e] = 0.f;

    const int mrow = tid >> 3;
    const int kchk = (tid & 7) << 2;

    auto load_tile = [&](int s, int k0) {
        uint32_t dA = sm_base + (uint32_t)(s * 2 * TILEW) * 4;
        uint32_t dB = dA + TILEW * 4;
        #pragma unroll
        for (int j = 0; j < 8; j++) {
            int m = mrow + 16 * j;
            cp_async16(dA + (uint32_t)(m * LDK + kchk) * 4,
                       Ap + (size_t)m * lda + k0 + kchk);
            cp_async16(dB + (uint32_t)(m * LDK + kchk) * 4,
                       Wp + (size_t)m * Kdim + k0 + kchk);
        }
        asm volatile("cp.async.commit_group;" ::: "memory");
    };

    const int niter = Kdim >> 5;
    load_tile(0, 0);

    for (int it = 0; it < niter; it++) {
        if (it + 1 < niter) {
            load_tile((it + 1) & 1, (it + 1) << 5);
            asm volatile("cp.async.wait_group 1;" ::: "memory");
        } else {
            asm volatile("cp.async.wait_group 0;" ::: "memory");
        }
        __syncthreads();

        const float* sA = sm + (it & 1) * 2 * TILEW;
        const float* sB = sA + TILEW;
        const uint32_t* uA = reinterpret_cast<const uint32_t*>(sA);

        #pragma unroll
        for (int s = 0; s < 4; s++) {
            const int k = 8 * s;
            uint32_t af[4][4], bf[8][2];
            #pragma unroll
            for (int mt = 0; mt < 4; mt++) {
                int m0 = wm * 64 + mt * 16 + g;
                if (ATF32) {
                    af[mt][0] = uA[m0 * LDK + k + tq];
                    af[mt][1] = uA[(m0 + 8) * LDK + k + tq];
                    af[mt][2] = uA[m0 * LDK + k + tq + 4];
                    af[mt][3] = uA[(m0 + 8) * LDK + k + tq + 4];
                } else {
                    af[mt][0] = f2tf(sA[m0 * LDK + k + tq]);
                    af[mt][1] = f2tf(sA[(m0 + 8) * LDK + k + tq]);
                    af[mt][2] = f2tf(sA[m0 * LDK + k + tq + 4]);
                    af[mt][3] = f2tf(sA[(m0 + 8) * LDK + k + tq + 4]);
                }
            }
            #pragma unroll
            for (int nt = 0; nt < 8; nt++) {
                int n0 = wn * 64 + nt * 8 + g;
                bf[nt][0] = f2tf(sB[n0 * LDK + k + tq]);
                bf[nt][1] = f2tf(sB[n0 * LDK + k + tq + 4]);
            }
            #pragma unroll
            for (int mt = 0; mt < 4; mt++)
                #pragma unroll
                for (int nt = 0; nt < 8; nt++)
                    mma_tf32(acc[mt][nt], af[mt], bf[nt]);
        }
        __syncthreads();
    }

    #pragma unroll
    for (int nt = 0; nt < 8; nt++) {
        int col = nBase + wn * 64 + nt * 8 + 2 * tq;
        float2 bv = *reinterpret_cast<const float2*>(&bias[col]);
        #pragma unroll
        for (int mt = 0; mt < 4; mt++) {
            size_t row = mBase + wm * 64 + mt * 16 + g;
            float v00 = acc[mt][nt][0] + bv.x, v01 = acc[mt][nt][1] + bv.y;
            float v10 = acc[mt][nt][2] + bv.x, v11 = acc[mt][nt][3] + bv.y;
            if (OUT == 2) {
                // fp16 transposed: Vt[b][d][t], d = col, t = row % T
                int bb = (int)(row >> 11);
                int t  = (int)(row & 2047);
                __half* base = g_Vt + ((size_t)bb * D_ + col) * T_ + t;
                base[0]      = __float2half(v00);
                base[T_]     = __float2half(v01);
                base[8]      = __float2half(v10);
                base[T_ + 8] = __float2half(v11);
            } else if (OUT == 1) {
                *reinterpret_cast<float2*>(&C[row * ldc + col]) =
                    make_float2(__uint_as_float(f2tf(v00)), __uint_as_float(f2tf(v01)));
                *reinterpret_cast<float2*>(&C[(row + 8) * ldc + col]) =
                    make_float2(__uint_as_float(f2tf(v10)), __uint_as_float(f2tf(v11)));
            } else {
                *reinterpret_cast<float2*>(&C[row * ldc + col])       = make_float2(v00, v01);
                *reinterpret_cast<float2*>(&C[(row + 8) * ldc + col]) = make_float2(v10, v11);
            }
        }
    }
}

// ---- fused Q/K/V/bias projections: one launch, per-block routing -----------
__global__ void __launch_bounds__(128) proj_fused_kernel(
    const float* __restrict__ Gm,
    const float* __restrict__ Wq, const float* __restrict__ bq,
    const float* __restrict__ Wk, const float* __restrict__ bk,
    const float* __restrict__ Wv, const float* __restrict__ bv,
    const float* __restrict__ Wg, const float* __restrict__ bg)
{
    extern __shared__ float sm[];
    const int bx = blockIdx.x;
    const size_t mB = (size_t)blockIdx.y * 128;
    if (bx < 8)
        gemm_core<true, 1>(g_hcat, D2_, Wq, D2_, bq, g_Q,    D_, mB, bx * 128, sm);
    else if (bx < 16)
        gemm_core<true, 1>(g_hcat, D2_, Wk, D2_, bk, g_K,    D_, mB, (bx - 8) * 128, sm);
    else if (bx < 24)
        gemm_core<true, 2>(g_hcat, D2_, Wv, D_,  bv, nullptr, 0, mB, (bx - 16) * 128, sm);
    else
        gemm_core<false, 0>(Gm,    DM_, Wg, DM_, bg, g_bias, T_, mB, (bx - 24) * 128, sm);
}

// ---- plain GEMM (output projection; A fp32, out fp32) ----------------------
__global__ void __launch_bounds__(128) gemm_tf32_cp_kernel(
    const float* __restrict__ A, int lda,
    const float* __restrict__ W,
    const float* __restrict__ bias,
    float* __restrict__ C, int ldc, int Kdim)
{
    extern __shared__ float sm[];
    gemm_core<false, 0>(A, lda, W, Kdim, bias, C, ldc,
                        (size_t)blockIdx.y * 128, blockIdx.x * 128, sm);
}

// ---------------- flash attention: tf32 QK^T + fp16 PV, smem-staged Q -------
// __launch_bounds__(128, 1): smem (88 KB) caps residency at 2 CTAs/SM anyway;
// give ptxas the full register budget so qa/o state is NOT spilled to local.
#define ALDK 68
#define VLD  36                       // uint pitch for fp16 V^T (64 tok = 32 u + pad)
#define PLD  68                       // uint pitch for Q-stage / packed-fp16 P
#define KWU  (64 * ALDK)              // 4352 uints
#define VWU  (64 * VLD)               // 2304 uints
#define STGU (KWU + VWU)              // 6656 uints per stage
#define PQW  (128 * PLD)              // 8704 uints (Q stage, then P)
#define ATTN_SMEM ((2 * STGU + PQW) * (int)sizeof(uint32_t))   // 88064 B

__global__ void __launch_bounds__(128, 1) attn_tf32_kernel() {
    extern __shared__ uint32_t smu[];
    uint32_t* P = smu + 2 * STGU;     // Q staging, then per-warp P slabs

    const int tid  = threadIdx.x;
    const int lane = tid & 31;
    const int warp = tid >> 5;
    const int g    = lane >> 2;
    const int tq   = lane & 3;
    const int b    = blockIdx.z;
    const int h    = blockIdx.y;
    const int q0   = blockIdx.x * 128;

    const uint32_t smb = smem_u32(smu);

    const float* __restrict__ Qg = g_Q + (size_t)b * T_ * D_ + (size_t)h * DK_;
    const float* __restrict__ Kg = g_K + (size_t)b * T_ * D_ + (size_t)h * DK_;
    const __half* __restrict__ Vtg =
        g_Vt + ((size_t)b * D_ + (size_t)h * DK_) * T_;
    const float* __restrict__ Bg = g_bias + ((size_t)b * T_ + q0) * T_;

    // async loader: K tile (tf32 bits, [token][dk]) + V^T tile (fp16, [dk][token])
    auto load_kv = [&](int st, int k0) {
        uint32_t dK = smb + (uint32_t)(st * STGU) * 4;
        uint32_t dV = dK + KWU * 4;
        #pragma unroll
        for (int j = 0; j < 8; j++) {
            int i = tid + 128 * j;
            int r = i >> 4, c4 = (i & 15) << 2;
            cp_async16(dK + (uint32_t)(r * ALDK + c4) * 4,
                       Kg + (size_t)(k0 + r) * D_ + c4);
        }
        #pragma unroll
        for (int j = 0; j < 4; j++) {
            int i = tid + 128 * j;
            int r = i >> 3, c = i & 7;           // r = dk row, c = 16B chunk (8 tokens)
            cp_async16(dV + (uint32_t)(r * VLD + 4 * c) * 4,
                       Vtg + (size_t)r * T_ + k0 + 8 * c);
        }
        asm volatile("cp.async.commit_group;" ::: "memory");
    };

    load_kv(0, 0);

    // stage Q (128 x 64 tf32 bits) into the P region (coalesced uint4)
    #pragma unroll
    for (int i = tid; i < 128 * 16; i += 128) {
        int r = i >> 4, c4 = (i & 15) << 2;
        uint4 v = *reinterpret_cast<const uint4*>(&Qg[(size_t)(q0 + r) * D_ + c4]);
        *reinterpret_cast<uint4*>(&P[r * PLD + c4]) = v;
    }
    __syncthreads();

    // Q fragments -> registers (smem source is clobbered by P below, so these
    // MUST stay register-resident)
    uint32_t qa0[8][4], qa1[8][4];
    {
        const uint32_t* Q0 = P + (warp * 32 + g) * PLD;
        const uint32_t* Q1 = P + (warp * 32 + 16 + g) * PLD;
        #pragma unroll
        for (int s = 0; s < 8; s++) {
            qa0[s][0] = Q0[8 * s + tq];
            qa0[s][1] = Q0[8 * PLD + 8 * s + tq];
            qa0[s][2] = Q0[8 * s + tq + 4];
            qa0[s][3] = Q0[8 * PLD + 8 * s + tq + 4];
            qa1[s][0] = Q1[8 * s + tq];
            qa1[s][1] = Q1[8 * PLD + 8 * s + tq];
            qa1[s][2] = Q1[8 * s + tq + 4];
            qa1[s][3] = Q1[8 * PLD + 8 * s + tq + 4];
        }
    }
    __syncthreads();

    float o0[8][4], o1[8][4];
    #pragma unroll
    for (int nt = 0; nt < 8; nt++)
        #pragma unroll
        for (int e = 0; e < 4; e++) { o0[nt][e] = 0.f; o1[nt][e] = 0.f; }
    float rs[4] = {0.f, 0.f, 0.f, 0.f};

    uint32_t* Pw = P + warp * 32 * PLD;
    const int niter = T_ / 64;

    for (int it = 0; it < niter; it++) {
        const int k0 = it * 64;
        if (it + 1 < niter) {
            load_kv((it + 1) & 1, k0 + 64);
            asm volatile("cp.async.wait_group 1;" ::: "memory");
        } else {
            asm volatile("cp.async.wait_group 0;" ::: "memory");
        }
        __syncthreads();

        const uint32_t* sK  = smu + (it & 1) * STGU;
        const uint32_t* sVt = sK + KWU;
        const float*    B0  = Bg + (size_t)(warp * 32 + g) * T_ + k0;

        // S = Q K^T (tf32, two nt columns per pass), shift-free softmax, pack P
        #pragma unroll
        for (int ntp = 0; ntp < 4; ntp++) {
            const int ntA = 2 * ntp, ntB = 2 * ntp + 1;
            const int cbA = ntA * 8 + 2 * tq, cbB = ntB * 8 + 2 * tq;

            float2 bA00 = *reinterpret_cast<const float2*>(&B0[cbA]);
            float2 bA01 = *reinterpret_cast<const float2*>(&B0[8  * T_ + cbA]);
            float2 bA10 = *reinterpret_cast<const float2*>(&B0[16 * T_ + cbA]);
            float2 bA11 = *reinterpret_cast<const float2*>(&B0[24 * T_ + cbA]);
            float2 bB00 = *reinterpret_cast<const float2*>(&B0[cbB]);
            float2 bB01 = *reinterpret_cast<const float2*>(&B0[8  * T_ + cbB]);
            float2 bB10 = *reinterpret_cast<const float2*>(&B0[16 * T_ + cbB]);
            float2 bB11 = *reinterpret_cast<const float2*>(&B0[24 * T_ + cbB]);

            float sA0[4] = {0.f,0.f,0.f,0.f}, sA1[4] = {0.f,0.f,0.f,0.f};
            float sB0[4] = {0.f,0.f,0.f,0.f}, sB1[4] = {0.f,0.f,0.f,0.f};
            #pragma unroll
            for (int s = 0; s < 8; s++) {
                const uint32_t* KrA = sK + (ntA * 8 + g) * ALDK + 8 * s + tq;
                const uint32_t* KrB = sK + (ntB * 8 + g) * ALDK + 8 * s + tq;
                uint32_t bbA[2] = { KrA[0], KrA[4] };
                uint32_t bbB[2] = { KrB[0], KrB[4] };
                mma_tf32(sA0, qa0[s], bbA);
                mma_tf32(sA1, qa1[s], bbA);
                mma_tf32(sB0, qa0[s], bbB);
                mma_tf32(sB1, qa1[s], bbB);
            }

            float pA00 = __expf(fmaf(sA0[0], 0.125f, bA00.x));
            float pA01 = __expf(fmaf(sA0[1], 0.125f, bA00.y));
            float pA02 = __expf(fmaf(sA0[2], 0.125f, bA01.x));
            float pA03 = __expf(fmaf(sA0[3], 0.125f, bA01.y));
            float pA10 = __expf(fmaf(sA1[0], 0.125f, bA10.x));
            float pA11 = __expf(fmaf(sA1[1], 0.125f, bA10.y));
            float pA12 = __expf(fmaf(sA1[2], 0.125f, bA11.x));
            float pA13 = __expf(fmaf(sA1[3], 0.125f, bA11.y));
            float pB00 = __expf(fmaf(sB0[0], 0.125f, bB00.x));
            float pB01 = __expf(fmaf(sB0[1], 0.125f, bB00.y));
            float pB02 = __expf(fmaf(sB0[2], 0.125f, bB01.x));
            float pB03 = __expf(fmaf(sB0[3], 0.125f, bB01.y));
            float pB10 = __expf(fmaf(sB1[0], 0.125f, bB10.x));
            float pB11 = __expf(fmaf(sB1[1], 0.125f, bB10.y));
            float pB12 = __expf(fmaf(sB1[2], 0.125f, bB11.x));
            float pB13 = __expf(fmaf(sB1[3], 0.125f, bB11.y));

            rs[0] += pA00 + pA01 + pB00 + pB01;
            rs[1] += pA02 + pA03 + pB02 + pB03;
            rs[2] += pA10 + pA11 + pB10 + pB11;
            rs[3] += pA12 + pA13 + pB12 + pB13;

            // packed fp16 P: uint col = col/2 = nt*4 + tq
            Pw[g * PLD        + ntA * 4 + tq] = pack_f16(pA00, pA01);
            Pw[(g + 8) * PLD  + ntA * 4 + tq] = pack_f16(pA02, pA03);
            Pw[(g + 16) * PLD + ntA * 4 + tq] = pack_f16(pA10, pA11);
            Pw[(g + 24) * PLD + ntA * 4 + tq] = pack_f16(pA12, pA13);
            Pw[g * PLD        + ntB * 4 + tq] = pack_f16(pB00, pB01);
            Pw[(g + 8) * PLD  + ntB * 4 + tq] = pack_f16(pB02, pB03);
            Pw[(g + 16) * PLD + ntB * 4 + tq] = pack_f16(pB10, pB11);
            Pw[(g + 24) * PLD + ntB * 4 + tq] = pack_f16(pB12, pB13);
        }
        __syncwarp();

        // O += P V  (fp16 m16n8k16: 4 k-steps of 16 tokens)
        #pragma unroll
        for (int s = 0; s < 4; s++) {
            uint32_t pa0[4], pa1[4];
            pa0[0] = Pw[g * PLD + 8 * s + tq];
            pa0[1] = Pw[(g + 8) * PLD + 8 * s + tq];
            pa0[2] = Pw[g * PLD + 8 * s + tq + 4];
            pa0[3] = Pw[(g + 8) * PLD + 8 * s + tq + 4];
            pa1[0] = Pw[(g + 16) * PLD + 8 * s + tq];
            pa1[1] = Pw[(g + 24) * PLD + 8 * s + tq];
            pa1[2] = Pw[(g + 16) * PLD + 8 * s + tq + 4];
            pa1[3] = Pw[(g + 24) * PLD + 8 * s + tq + 4];
            #pragma unroll
            for (int nt = 0; nt < 8; nt++) {
                uint32_t bb[2];
                bb[0] = sVt[(nt * 8 + g) * VLD + 8 * s + tq];
                bb[1] = sVt[(nt * 8 + g) * VLD + 8 * s + tq + 4];
                mma_f16(o0[nt], pa0, bb);
                mma_f16(o1[nt], pa1, bb);
            }
        }
        __syncthreads();
    }

    #pragma unroll
    for (int e = 0; e < 4; e++) {
        rs[e] += __shfl_xor_sync(0xffffffffu, rs[e], 1);
        rs[e] += __shfl_xor_sync(0xffffffffu, rs[e], 2);
    }
    float inv0 = 1.0f / rs[0], inv1 = 1.0f / rs[1];
    float inv2 = 1.0f / rs[2], inv3 = 1.0f / rs[3];

    float* Og = g_O + (size_t)b * T_ * D_ + (size_t)h * DK_;
    size_t r0 = (size_t)q0 + warp * 32 + g;
    #pragma unroll
    for (int nt = 0; nt < 8; nt++) {
        int col = nt * 8 + 2 * tq;
        *reinterpret_cast<float2*>(&Og[r0 * D_ + col]) =
            make_float2(o0[nt][0] * inv0, o0[nt][1] * inv0);
        *reinterpret_cast<float2*>(&Og[(r0 + 8) * D_ + col]) =
            make_float2(o0[nt][2] * inv1, o0[nt][3] * inv1);
        *reinterpret_cast<float2*>(&Og[(r0 + 16) * D_ + col]) =
            make_float2(o1[nt][0] * inv2, o1[nt][1] * inv2);
        *reinterpret_cast<float2*>(&Og[(r0 + 24) * D_ + col]) =
            make_float2(o1[nt][2] * inv3, o1[nt][3] * inv3);
    }
}

// ---------------- launch ----------------------------------------------------
extern "C" void kernel_launch(void* const* d_in, const int* in_sizes, int n_in,
                              void* d_out, int out_size) {
    const float* Hx = (const float*)d_in[0];
    const float* Hf = (const float*)d_in[1];
    const float* Gm = (const float*)d_in[2];
    const float* Wg = (const float*)d_in[3];
    const float* bg = (const float*)d_in[4];
    const float* Wq = (const float*)d_in[5];
    const float* bq = (const float*)d_in[6];
    const float* Wk = (const float*)d_in[7];
    const float* bk = (const float*)d_in[8];
    const float* Wv = (const float*)d_in[9];
    const float* bv = (const float*)d_in[10];
    const float* Wo = (const float*)d_in[11];
    const float* bo = (const float*)d_in[12];
    float* out = (float*)d_out;

    float* O;
    cudaGetSymbolAddress((void**)&O, g_O);

    cudaFuncSetAttribute(proj_fused_kernel,
                         cudaFuncAttributeMaxDynamicSharedMemorySize, GEMM_SMEM);
    cudaFuncSetAttribute(gemm_tf32_cp_kernel,
                         cudaFuncAttributeMaxDynamicSharedMemorySize, GEMM_SMEM);
    cudaFuncSetAttribute(attn_tf32_kernel,
                         cudaFuncAttributeMaxDynamicSharedMemorySize, ATTN_SMEM);

    // 1) build hcat = [hx | Hf] (as tf32 bits)
    transpose_hx_kernel<<<dim3(T_ / 32, D_ / 32, B_), dim3(32, 8)>>>(Hx);
    copy_hf_kernel<<<(B_ * T_ * (D_ / 4) + 255) / 256, 256>>>((const float4*)Hf);

    // 2) all projections in ONE launch (Q/K tf32 bits, V -> fp16 transposed)
    proj_fused_kernel<<<dim3(40, 32), 128, GEMM_SMEM>>>(
        Gm, Wq, bq, Wk, bk, Wv, bv, Wg, bg);

    // 3) attention
    attn_tf32_kernel<<<dim3(T_ / 128, H_, B_), 128, ATTN_SMEM>>>();

    // 4) output projection (fp32 in/out)
    gemm_tf32_cp_kernel<<<dim3(D_ / 128, 32), 128, GEMM_SMEM>>>(O, D_, Wo, bo, out, D_, D_);
}

// round 14
// speedup vs baseline: 1.4963x; 1.0975x over previous
#include <cuda_runtime.h>
#include <cuda_fp16.h>
#include <math_constants.h>
#include <cstdint>

#define B_   2
#define T_   2048
#define D_   1024
#define H_   16
#define DK_  64
#define DM_  256
#define D2_  2048

// ---------------- scratch (device globals; no allocation allowed) ----------
// g_hcat holds tf32 BITS; g_Q, g_K hold fp16 [b][t][d]; g_Vt holds fp16
// TRANSPOSED [b][d][t]; g_bias, g_O hold fp32.
__device__ float  g_hcat[(size_t)B_ * T_ * D2_];
__device__ __half g_Q [(size_t)B_ * T_ * D_];
__device__ __half g_K [(size_t)B_ * T_ * D_];
__device__ __half g_Vt[(size_t)B_ * D_ * T_];
__device__ float  g_bias[(size_t)B_ * T_ * T_];
__device__ float  g_O [(size_t)B_ * T_ * D_];

// ---------------- helpers ----------------------------------------------------
__device__ __forceinline__ uint32_t f2tf(float x) {
    uint32_t u; asm("cvt.rna.tf32.f32 %0, %1;" : "=r"(u) : "f"(x)); return u;
}
__device__ __forceinline__ uint32_t pack_f16(float lo, float hi) {
    uint32_t u; asm("cvt.rn.f16x2.f32 %0, %1, %2;" : "=r"(u) : "f"(hi), "f"(lo)); return u;
}
__device__ __forceinline__ void mma_tf32(float* c, const uint32_t* a, const uint32_t* b) {
    asm volatile("mma.sync.aligned.m16n8k8.row.col.f32.tf32.tf32.f32 "
        "{%0,%1,%2,%3}, {%4,%5,%6,%7}, {%8,%9}, {%0,%1,%2,%3};\n"
        : "+f"(c[0]), "+f"(c[1]), "+f"(c[2]), "+f"(c[3])
        : "r"(a[0]), "r"(a[1]), "r"(a[2]), "r"(a[3]), "r"(b[0]), "r"(b[1]));
}
__device__ __forceinline__ void mma_f16(float* c, const uint32_t* a, const uint32_t* b) {
    asm volatile("mma.sync.aligned.m16n8k16.row.col.f32.f16.f16.f32 "
        "{%0,%1,%2,%3}, {%4,%5,%6,%7}, {%8,%9}, {%0,%1,%2,%3};\n"
        : "+f"(c[0]), "+f"(c[1]), "+f"(c[2]), "+f"(c[3])
        : "r"(a[0]), "r"(a[1]), "r"(a[2]), "r"(a[3]), "r"(b[0]), "r"(b[1]));
}
__device__ __forceinline__ uint32_t smem_u32(const void* p) {
    uint32_t a;
    asm("{ .reg .u64 t; cvta.to.shared.u64 t, %1; cvt.u32.u64 %0, t; }" : "=r"(a) : "l"(p));
    return a;
}
__device__ __forceinline__ void cp_async16(uint32_t dst, const void* src) {
    asm volatile("cp.async.cg.shared.global [%0], [%1], 16;"
                 :: "r"(dst), "l"(src) : "memory");
}

// ---------------- hx transpose: Hx (B,D,T,1) -> g_hcat[:, 0:D] (tf32 bits) --
__global__ void transpose_hx_kernel(const float* __restrict__ Hx) {
    __shared__ float tile[32][33];
    int b  = blockIdx.z;
    int d0 = blockIdx.y * 32;
    int t0 = blockIdx.x * 32;
    #pragma unroll
    for (int yy = threadIdx.y; yy < 32; yy += 8)
        tile[yy][threadIdx.x] = Hx[((size_t)(b * D_ + d0 + yy)) * T_ + t0 + threadIdx.x];
    __syncthreads();
    #pragma unroll
    for (int yy = threadIdx.y; yy < 32; yy += 8)
        g_hcat[((size_t)(b * T_ + t0 + yy)) * D2_ + d0 + threadIdx.x] =
            __uint_as_float(f2tf(tile[threadIdx.x][yy]));
}

__global__ void copy_hf_kernel(const float4* __restrict__ Hf) {
    int idx = blockIdx.x * blockDim.x + threadIdx.x;
    if (idx >= B_ * T_ * (D_ / 4)) return;
    int row  = idx / (D_ / 4);
    int col4 = idx % (D_ / 4);
    float4 v = Hf[idx];
    float4 o = make_float4(__uint_as_float(f2tf(v.x)), __uint_as_float(f2tf(v.y)),
                           __uint_as_float(f2tf(v.z)), __uint_as_float(f2tf(v.w)));
    *reinterpret_cast<float4*>(&g_hcat[(size_t)row * D2_ + D_ + col4 * 4]) = o;
}

// ---------------- tf32 GEMM core (round-4 proven config) --------------------
// ATF32: A already holds tf32 bits.
// OUT: 0 = fp32 to C, 1 = fp16 packed to C (C is __half*, ldc in halves),
//      2 = fp16 TRANSPOSED into g_Vt.
#define LDK   36
#define TILEW (128 * LDK)
#define GEMM_SMEM (2 * 2 * TILEW * 4)             // 73728 B

template <bool ATF32, int OUT>
__device__ __forceinline__ void gemm_core(
    const float* __restrict__ A, int lda,
    const float* __restrict__ W, int Kdim,
    const float* __restrict__ bias,
    void* __restrict__ Cv, int ldc,
    size_t mBase, int nBase, float* sm)
{
    const uint32_t sm_base = smem_u32(sm);
    const int tid  = threadIdx.x;
    const int lane = tid & 31;
    const int warp = tid >> 5;
    const int g    = lane >> 2;
    const int tq   = lane & 3;
    const int wm   = warp & 1;
    const int wn   = warp >> 1;

    const float* Ap = A + mBase * lda;
    const float* Wp = W + (size_t)nBase * Kdim;

    float acc[4][8][4];
    #pragma unroll
    for (int mt = 0; mt < 4; mt++)
        #pragma unroll
        for (int nt = 0; nt < 8; nt++)
            #pragma unroll
            for (int e = 0; e < 4; e++) acc[mt][nt][e] = 0.f;

    const int mrow = tid >> 3;
    const int kchk = (tid & 7) << 2;

    auto load_tile = [&](int s, int k0) {
        uint32_t dA = sm_base + (uint32_t)(s * 2 * TILEW) * 4;
        uint32_t dB = dA + TILEW * 4;
        #pragma unroll
        for (int j = 0; j < 8; j++) {
            int m = mrow + 16 * j;
            cp_async16(dA + (uint32_t)(m * LDK + kchk) * 4,
                       Ap + (size_t)m * lda + k0 + kchk);
            cp_async16(dB + (uint32_t)(m * LDK + kchk) * 4,
                       Wp + (size_t)m * Kdim + k0 + kchk);
        }
        asm volatile("cp.async.commit_group;" ::: "memory");
    };

    const int niter = Kdim >> 5;
    load_tile(0, 0);

    for (int it = 0; it < niter; it++) {
        if (it + 1 < niter) {
            load_tile((it + 1) & 1, (it + 1) << 5);
            asm volatile("cp.async.wait_group 1;" ::: "memory");
        } else {
            asm volatile("cp.async.wait_group 0;" ::: "memory");
        }
        __syncthreads();

        const float* sA = sm + (it & 1) * 2 * TILEW;
        const float* sB = sA + TILEW;
        const uint32_t* uA = reinterpret_cast<const uint32_t*>(sA);

        #pragma unroll
        for (int s = 0; s < 4; s++) {
            const int k = 8 * s;
            uint32_t af[4][4], bf[8][2];
            #pragma unroll
            for (int mt = 0; mt < 4; mt++) {
                int m0 = wm * 64 + mt * 16 + g;
                if (ATF32) {
                    af[mt][0] = uA[m0 * LDK + k + tq];
                    af[mt][1] = uA[(m0 + 8) * LDK + k + tq];
                    af[mt][2] = uA[m0 * LDK + k + tq + 4];
                    af[mt][3] = uA[(m0 + 8) * LDK + k + tq + 4];
                } else {
                    af[mt][0] = f2tf(sA[m0 * LDK + k + tq]);
                    af[mt][1] = f2tf(sA[(m0 + 8) * LDK + k + tq]);
                    af[mt][2] = f2tf(sA[m0 * LDK + k + tq + 4]);
                    af[mt][3] = f2tf(sA[(m0 + 8) * LDK + k + tq + 4]);
                }
            }
            #pragma unroll
            for (int nt = 0; nt < 8; nt++) {
                int n0 = wn * 64 + nt * 8 + g;
                bf[nt][0] = f2tf(sB[n0 * LDK + k + tq]);
                bf[nt][1] = f2tf(sB[n0 * LDK + k + tq + 4]);
            }
            #pragma unroll
            for (int mt = 0; mt < 4; mt++)
                #pragma unroll
                for (int nt = 0; nt < 8; nt++)
                    mma_tf32(acc[mt][nt], af[mt], bf[nt]);
        }
        __syncthreads();
    }

    #pragma unroll
    for (int nt = 0; nt < 8; nt++) {
        int col = nBase + wn * 64 + nt * 8 + 2 * tq;
        float2 bv = *reinterpret_cast<const float2*>(&bias[col]);
        #pragma unroll
        for (int mt = 0; mt < 4; mt++) {
            size_t row = mBase + wm * 64 + mt * 16 + g;
            float v00 = acc[mt][nt][0] + bv.x, v01 = acc[mt][nt][1] + bv.y;
            float v10 = acc[mt][nt][2] + bv.x, v11 = acc[mt][nt][3] + bv.y;
            if (OUT == 2) {
                // fp16 transposed: Vt[b][d][t], d = col, t = row % T
                int bb = (int)(row >> 11);
                int t  = (int)(row & 2047);
                __half* base = g_Vt + ((size_t)bb * D_ + col) * T_ + t;
                base[0]      = __float2half(v00);
                base[T_]     = __float2half(v01);
                base[8]      = __float2half(v10);
                base[T_ + 8] = __float2half(v11);
            } else if (OUT == 1) {
                uint32_t* Ch = reinterpret_cast<uint32_t*>(Cv);
                Ch[row * (ldc >> 1) + (col >> 1)]       = pack_f16(v00, v01);
                Ch[(row + 8) * (ldc >> 1) + (col >> 1)] = pack_f16(v10, v11);
            } else {
                float* C = reinterpret_cast<float*>(Cv);
                *reinterpret_cast<float2*>(&C[row * ldc + col])       = make_float2(v00, v01);
                *reinterpret_cast<float2*>(&C[(row + 8) * ldc + col]) = make_float2(v10, v11);
            }
        }
    }
}

// ---- fused Q/K/V/bias projections: one launch, per-block routing -----------
__global__ void __launch_bounds__(128) proj_fused_kernel(
    const float* __restrict__ Gm,
    const float* __restrict__ Wq, const float* __restrict__ bq,
    const float* __restrict__ Wk, const float* __restrict__ bk,
    const float* __restrict__ Wv, const float* __restrict__ bv,
    const float* __restrict__ Wg, const float* __restrict__ bg)
{
    extern __shared__ float sm[];
    const int bx = blockIdx.x;
    const size_t mB = (size_t)blockIdx.y * 128;
    if (bx < 8)
        gemm_core<true, 1>(g_hcat, D2_, Wq, D2_, bq, g_Q,    D_, mB, bx * 128, sm);
    else if (bx < 16)
        gemm_core<true, 1>(g_hcat, D2_, Wk, D2_, bk, g_K,    D_, mB, (bx - 8) * 128, sm);
    else if (bx < 24)
        gemm_core<true, 2>(g_hcat, D2_, Wv, D_,  bv, nullptr, 0, mB, (bx - 16) * 128, sm);
    else
        gemm_core<false, 0>(Gm,    DM_, Wg, DM_, bg, g_bias, T_, mB, (bx - 24) * 128, sm);
}

// ---- plain GEMM (output projection; A fp32, out fp32) ----------------------
__global__ void __launch_bounds__(128) gemm_tf32_cp_kernel(
    const float* __restrict__ A, int lda,
    const float* __restrict__ W,
    const float* __restrict__ bias,
    float* __restrict__ C, int ldc, int Kdim)
{
    extern __shared__ float sm[];
    gemm_core<false, 0>(A, lda, W, Kdim, bias, C, ldc,
                        (size_t)blockIdx.y * 128, blockIdx.x * 128, sm);
}

// ---------------- flash attention: all-fp16 mma (QK^T k16 + PV k16) ---------
// Q/K/V all fp16; Q staged through the P region (forces register residency);
// __launch_bounds__(128,1) prevents register spills (round-13 lesson).
#define KLD  36                       // uint pitch for fp16 K tile rows
#define VLD  36                       // uint pitch for fp16 V^T rows
#define PLD  36                       // uint pitch for Q-stage / packed-fp16 P
#define KWU  (64 * KLD)               // 2304 uints
#define VWU  (64 * VLD)               // 2304 uints
#define STGU (KWU + VWU)              // 4608 uints per stage
#define PQW  (128 * PLD)              // 4608 uints
#define ATTN_SMEM ((2 * STGU + PQW) * (int)sizeof(uint32_t))   // 55296 B

__global__ void __launch_bounds__(128, 1) attn_f16_kernel() {
    extern __shared__ uint32_t smu[];
    uint32_t* P = smu + 2 * STGU;     // Q staging, then per-warp P slabs

    const int tid  = threadIdx.x;
    const int lane = tid & 31;
    const int warp = tid >> 5;
    const int g    = lane >> 2;
    const int tq   = lane & 3;
    const int b    = blockIdx.z;
    const int h    = blockIdx.y;
    const int q0   = blockIdx.x * 128;

    const uint32_t smb = smem_u32(smu);

    // fp16 sources viewed as packed uints (D_ and DK_ even)
    const uint32_t* __restrict__ Qg =
        reinterpret_cast<const uint32_t*>(g_Q) + ((size_t)b * T_ * D_ + (size_t)h * DK_) / 2;
    const uint32_t* __restrict__ Kg =
        reinterpret_cast<const uint32_t*>(g_K) + ((size_t)b * T_ * D_ + (size_t)h * DK_) / 2;
    const __half*   __restrict__ Vtg =
        g_Vt + ((size_t)b * D_ + (size_t)h * DK_) * T_;
    const float*    __restrict__ Bg = g_bias + ((size_t)b * T_ + q0) * T_;

    const int ldq = D_ / 2;          // row stride in uints

    // async loader: K tile (fp16 [token][dk]) + V^T tile (fp16 [dk][token])
    auto load_kv = [&](int st, int k0) {
        uint32_t dK = smb + (uint32_t)(st * STGU) * 4;
        uint32_t dV = dK + KWU * 4;
        #pragma unroll
        for (int j = 0; j < 4; j++) {
            int i = tid + 128 * j;
            int r = i >> 3, c = i & 7;           // r = token row, c = 16B chunk
            cp_async16(dK + (uint32_t)(r * KLD + 4 * c) * 4,
                       Kg + (size_t)(k0 + r) * ldq + 4 * c);
        }
        #pragma unroll
        for (int j = 0; j < 4; j++) {
            int i = tid + 128 * j;
            int r = i >> 3, c = i & 7;           // r = dk row, c = 16B chunk (8 tok)
            cp_async16(dV + (uint32_t)(r * VLD + 4 * c) * 4,
                       Vtg + (size_t)r * T_ + k0 + 8 * c);
        }
        asm volatile("cp.async.commit_group;" ::: "memory");
    };

    load_kv(0, 0);

    // stage Q (128 rows x 32 uints fp16) into the P region
    #pragma unroll
    for (int i = tid; i < 128 * 8; i += 128) {
        int r = i >> 3, c4 = (i & 7) << 2;
        uint4 v = *reinterpret_cast<const uint4*>(&Qg[(size_t)(q0 + r) * ldq + c4]);
        *reinterpret_cast<uint4*>(&P[r * PLD + c4]) = v;
    }
    __syncthreads();

    // Q fragments -> registers (clobbered by P below => must stay resident)
    uint32_t qa0[4][4], qa1[4][4];
    {
        const uint32_t* Q0 = P + (warp * 32 + g) * PLD;
        const uint32_t* Q1 = P + (warp * 32 + 16 + g) * PLD;
        #pragma unroll
        for (int s = 0; s < 4; s++) {
            qa0[s][0] = Q0[8 * s + tq];
            qa0[s][1] = Q0[8 * PLD + 8 * s + tq];
            qa0[s][2] = Q0[8 * s + tq + 4];
            qa0[s][3] = Q0[8 * PLD + 8 * s + tq + 4];
            qa1[s][0] = Q1[8 * s + tq];
            qa1[s][1] = Q1[8 * PLD + 8 * s + tq];
            qa1[s][2] = Q1[8 * s + tq + 4];
            qa1[s][3] = Q1[8 * PLD + 8 * s + tq + 4];
        }
    }
    __syncthreads();

    float o0[8][4], o1[8][4];
    #pragma unroll
    for (int nt = 0; nt < 8; nt++)
        #pragma unroll
        for (int e = 0; e < 4; e++) { o0[nt][e] = 0.f; o1[nt][e] = 0.f; }
    float rs[4] = {0.f, 0.f, 0.f, 0.f};

    uint32_t* Pw = P + warp * 32 * PLD;
    const int niter = T_ / 64;

    for (int it = 0; it < niter; it++) {
        const int k0 = it * 64;
        if (it + 1 < niter) {
            load_kv((it + 1) & 1, k0 + 64);
            asm volatile("cp.async.wait_group 1;" ::: "memory");
        } else {
            asm volatile("cp.async.wait_group 0;" ::: "memory");
        }
        __syncthreads();

        const uint32_t* sK  = smu + (it & 1) * STGU;
        const uint32_t* sVt = sK + KWU;
        const float*    B0  = Bg + (size_t)(warp * 32 + g) * T_ + k0;

        // S = Q K^T (fp16 k16, two nt columns per pass), softmax, pack P
        #pragma unroll
        for (int ntp = 0; ntp < 4; ntp++) {
            const int ntA = 2 * ntp, ntB = 2 * ntp + 1;
            const int cbA = ntA * 8 + 2 * tq, cbB = ntB * 8 + 2 * tq;

            float2 bA00 = *reinterpret_cast<const float2*>(&B0[cbA]);
            float2 bA01 = *reinterpret_cast<const float2*>(&B0[8  * T_ + cbA]);
            float2 bA10 = *reinterpret_cast<const float2*>(&B0[16 * T_ + cbA]);
            float2 bA11 = *reinterpret_cast<const float2*>(&B0[24 * T_ + cbA]);
            float2 bB00 = *reinterpret_cast<const float2*>(&B0[cbB]);
            float2 bB01 = *reinterpret_cast<const float2*>(&B0[8  * T_ + cbB]);
            float2 bB10 = *reinterpret_cast<const float2*>(&B0[16 * T_ + cbB]);
            float2 bB11 = *reinterpret_cast<const float2*>(&B0[24 * T_ + cbB]);

            float sA0[4] = {0.f,0.f,0.f,0.f}, sA1[4] = {0.f,0.f,0.f,0.f};
            float sB0[4] = {0.f,0.f,0.f,0.f}, sB1[4] = {0.f,0.f,0.f,0.f};
            #pragma unroll
            for (int s = 0; s < 4; s++) {
                const uint32_t* KrA = sK + (ntA * 8 + g) * KLD + 8 * s + tq;
                const uint32_t* KrB = sK + (ntB * 8 + g) * KLD + 8 * s + tq;
                uint32_t bbA[2] = { KrA[0], KrA[4] };
                uint32_t bbB[2] = { KrB[0], KrB[4] };
                mma_f16(sA0, qa0[s], bbA);
                mma_f16(sA1, qa1[s], bbA);
                mma_f16(sB0, qa0[s], bbB);
                mma_f16(sB1, qa1[s], bbB);
            }

            float pA00 = __expf(fmaf(sA0[0], 0.125f, bA00.x));
            float pA01 = __expf(fmaf(sA0[1], 0.125f, bA00.y));
            float pA02 = __expf(fmaf(sA0[2], 0.125f, bA01.x));
            float pA03 = __expf(fmaf(sA0[3], 0.125f, bA01.y));
            float pA10 = __expf(fmaf(sA1[0], 0.125f, bA10.x));
            float pA11 = __expf(fmaf(sA1[1], 0.125f, bA10.y));
            float pA12 = __expf(fmaf(sA1[2], 0.125f, bA11.x));
            float pA13 = __expf(fmaf(sA1[3], 0.125f, bA11.y));
            float pB00 = __expf(fmaf(sB0[0], 0.125f, bB00.x));
            float pB01 = __expf(fmaf(sB0[1], 0.125f, bB00.y));
            float pB02 = __expf(fmaf(sB0[2], 0.125f, bB01.x));
            float pB03 = __expf(fmaf(sB0[3], 0.125f, bB01.y));
            float pB10 = __expf(fmaf(sB1[0], 0.125f, bB10.x));
            float pB11 = __expf(fmaf(sB1[1], 0.125f, bB10.y));
            float pB12 = __expf(fmaf(sB1[2], 0.125f, bB11.x));
            float pB13 = __expf(fmaf(sB1[3], 0.125f, bB11.y));

            rs[0] += pA00 + pA01 + pB00 + pB01;
            rs[1] += pA02 + pA03 + pB02 + pB03;
            rs[2] += pA10 + pA11 + pB10 + pB11;
            rs[3] += pA12 + pA13 + pB12 + pB13;

            Pw[g * PLD        + ntA * 4 + tq] = pack_f16(pA00, pA01);
            Pw[(g + 8) * PLD  + ntA * 4 + tq] = pack_f16(pA02, pA03);
            Pw[(g + 16) * PLD + ntA * 4 + tq] = pack_f16(pA10, pA11);
            Pw[(g + 24) * PLD + ntA * 4 + tq] = pack_f16(pA12, pA13);
            Pw[g * PLD        + ntB * 4 + tq] = pack_f16(pB00, pB01);
            Pw[(g + 8) * PLD  + ntB * 4 + tq] = pack_f16(pB02, pB03);
            Pw[(g + 16) * PLD + ntB * 4 + tq] = pack_f16(pB10, pB11);
            Pw[(g + 24) * PLD + ntB * 4 + tq] = pack_f16(pB12, pB13);
        }
        __syncwarp();

        // O += P V  (fp16 m16n8k16: 4 k-steps of 16 tokens)
        #pragma unroll
        for (int s = 0; s < 4; s++) {
            uint32_t pa0[4], pa1[4];
            pa0[0] = Pw[g * PLD + 8 * s + tq];
            pa0[1] = Pw[(g + 8) * PLD + 8 * s + tq];
            pa0[2] = Pw[g * PLD + 8 * s + tq + 4];
            pa0[3] = Pw[(g + 8) * PLD + 8 * s + tq + 4];
            pa1[0] = Pw[(g + 16) * PLD + 8 * s + tq];
            pa1[1] = Pw[(g + 24) * PLD + 8 * s + tq];
            pa1[2] = Pw[(g + 16) * PLD + 8 * s + tq + 4];
            pa1[3] = Pw[(g + 24) * PLD + 8 * s + tq + 4];
            #pragma unroll
            for (int nt = 0; nt < 8; nt++) {
                uint32_t bb[2];
                bb[0] = sVt[(nt * 8 + g) * VLD + 8 * s + tq];
                bb[1] = sVt[(nt * 8 + g) * VLD + 8 * s + tq + 4];
                mma_f16(o0[nt], pa0, bb);
                mma_f16(o1[nt], pa1, bb);
            }
        }
        __syncthreads();
    }

    #pragma unroll
    for (int e = 0; e < 4; e++) {
        rs[e] += __shfl_xor_sync(0xffffffffu, rs[e], 1);
        rs[e] += __shfl_xor_sync(0xffffffffu, rs[e], 2);
    }
    float inv0 = 1.0f / rs[0], inv1 = 1.0f / rs[1];
    float inv2 = 1.0f / rs[2], inv3 = 1.0f / rs[3];

    float* Og = g_O + (size_t)b * T_ * D_ + (size_t)h * DK_;
    size_t r0 = (size_t)q0 + warp * 32 + g;
    #pragma unroll
    for (int nt = 0; nt < 8; nt++) {
        int col = nt * 8 + 2 * tq;
        *reinterpret_cast<float2*>(&Og[r0 * D_ + col]) =
            make_float2(o0[nt][0] * inv0, o0[nt][1] * inv0);
        *reinterpret_cast<float2*>(&Og[(r0 + 8) * D_ + col]) =
            make_float2(o0[nt][2] * inv1, o0[nt][3] * inv1);
        *reinterpret_cast<float2*>(&Og[(r0 + 16) * D_ + col]) =
            make_float2(o1[nt][0] * inv2, o1[nt][1] * inv2);
        *reinterpret_cast<float2*>(&Og[(r0 + 24) * D_ + col]) =
            make_float2(o1[nt][2] * inv3, o1[nt][3] * inv3);
    }
}

// ---------------- launch ----------------------------------------------------
extern "C" void kernel_launch(void* const* d_in, const int* in_sizes, int n_in,
                              void* d_out, int out_size) {
    const float* Hx = (const float*)d_in[0];
    const float* Hf = (const float*)d_in[1];
    const float* Gm = (const float*)d_in[2];
    const float* Wg = (const float*)d_in[3];
    const float* bg = (const float*)d_in[4];
    const float* Wq = (const float*)d_in[5];
    const float* bq = (const float*)d_in[6];
    const float* Wk = (const float*)d_in[7];
    const float* bk = (const float*)d_in[8];
    const float* Wv = (const float*)d_in[9];
    const float* bv = (const float*)d_in[10];
    const float* Wo = (const float*)d_in[11];
    const float* bo = (const float*)d_in[12];
    float* out = (float*)d_out;

    float* O;
    cudaGetSymbolAddress((void**)&O, g_O);

    cudaFuncSetAttribute(proj_fused_kernel,
                         cudaFuncAttributeMaxDynamicSharedMemorySize, GEMM_SMEM);
    cudaFuncSetAttribute(gemm_tf32_cp_kernel,
                         cudaFuncAttributeMaxDynamicSharedMemorySize, GEMM_SMEM);
    cudaFuncSetAttribute(attn_f16_kernel,
                         cudaFuncAttributeMaxDynamicSharedMemorySize, ATTN_SMEM);

    // 1) build hcat = [hx | Hf] (as tf32 bits)
    transpose_hx_kernel<<<dim3(T_ / 32, D_ / 32, B_), dim3(32, 8)>>>(Hx);
    copy_hf_kernel<<<(B_ * T_ * (D_ / 4) + 255) / 256, 256>>>((const float4*)Hf);

    // 2) all projections in ONE launch (Q/K -> fp16, V -> fp16 transposed)
    proj_fused_kernel<<<dim3(40, 32), 128, GEMM_SMEM>>>(
        Gm, Wq, bq, Wk, bk, Wv, bv, Wg, bg);

    // 3) attention (all-fp16 tensor path)
    attn_f16_kernel<<<dim3(T_ / 128, H_, B_), 128, ATTN_SMEM>>>();

    // 4) output projection (fp32 in/out)
    gemm_tf32_cp_kernel<<<dim3(D_ / 128, 32), 128, GEMM_SMEM>>>(O, D_, Wo, bo, out, D_, D_);
}

// round 15
// speedup vs baseline: 2.1069x; 1.4081x over previous
#include <cuda_runtime.h>
#include <cuda_fp16.h>
#include <math_constants.h>
#include <cstdint>

#define B_   2
#define T_   2048
#define D_   1024
#define H_   16
#define DK_  64
#define DM_  256
#define D2_  2048

// ---------------- scratch (device globals; no allocation allowed) ----------
// Everything tensor-op-facing is fp16; g_bias and final out are fp32.
__device__ __half g_hcat[(size_t)B_ * T_ * D2_];
__device__ __half g_Q  [(size_t)B_ * T_ * D_];
__device__ __half g_K  [(size_t)B_ * T_ * D_];
__device__ __half g_Vt [(size_t)B_ * D_ * T_];
__device__ __half g_O  [(size_t)B_ * T_ * D_];
__device__ float  g_bias[(size_t)B_ * T_ * T_];
// fp16 copies of weights / Gm
__device__ __half g_Wq[(size_t)D_ * D2_];
__device__ __half g_Wk[(size_t)D_ * D2_];
__device__ __half g_Wv[(size_t)D_ * D_];
__device__ __half g_Wo[(size_t)D_ * D_];
__device__ __half g_Wg[(size_t)T_ * DM_];
__device__ __half g_Gm[(size_t)B_ * T_ * DM_];

// ---------------- helpers ----------------------------------------------------
__device__ __forceinline__ uint32_t pack_f16(float lo, float hi) {
    uint32_t u; asm("cvt.rn.f16x2.f32 %0, %1, %2;" : "=r"(u) : "f"(hi), "f"(lo)); return u;
}
__device__ __forceinline__ void mma_f16(float* c, const uint32_t* a, const uint32_t* b) {
    asm volatile("mma.sync.aligned.m16n8k16.row.col.f32.f16.f16.f32 "
        "{%0,%1,%2,%3}, {%4,%5,%6,%7}, {%8,%9}, {%0,%1,%2,%3};\n"
        : "+f"(c[0]), "+f"(c[1]), "+f"(c[2]), "+f"(c[3])
        : "r"(a[0]), "r"(a[1]), "r"(a[2]), "r"(a[3]), "r"(b[0]), "r"(b[1]));
}
__device__ __forceinline__ uint32_t smem_u32(const void* p) {
    uint32_t a;
    asm("{ .reg .u64 t; cvta.to.shared.u64 t, %1; cvt.u32.u64 %0, t; }" : "=r"(a) : "l"(p));
    return a;
}
__device__ __forceinline__ void cp_async16(uint32_t dst, const void* src) {
    asm volatile("cp.async.cg.shared.global [%0], [%1], 16;"
                 :: "r"(dst), "l"(src) : "memory");
}

// ---------------- fp32 -> fp16 conversion (weights, Gm) ---------------------
__global__ void cvt_f16_kernel(const float4* __restrict__ src,
                               uint2* __restrict__ dst, int n4) {
    int i = blockIdx.x * blockDim.x + threadIdx.x;
    if (i >= n4) return;
    float4 v = src[i];
    dst[i] = make_uint2(pack_f16(v.x, v.y), pack_f16(v.z, v.w));
}

// ---------------- hx transpose: Hx (B,D,T,1) -> g_hcat[:, 0:D] (fp16) -------
__global__ void transpose_hx_kernel(const float* __restrict__ Hx) {
    __shared__ float tile[32][33];
    int b  = blockIdx.z;
    int d0 = blockIdx.y * 32;
    int t0 = blockIdx.x * 32;
    #pragma unroll
    for (int yy = threadIdx.y; yy < 32; yy += 8)
        tile[yy][threadIdx.x] = Hx[((size_t)(b * D_ + d0 + yy)) * T_ + t0 + threadIdx.x];
    __syncthreads();
    #pragma unroll
    for (int yy = threadIdx.y; yy < 32; yy += 8)
        g_hcat[((size_t)(b * T_ + t0 + yy)) * D2_ + d0 + threadIdx.x] =
            __float2half(tile[threadIdx.x][yy]);
}

__global__ void copy_hf_kernel(const float4* __restrict__ Hf) {
    int idx = blockIdx.x * blockDim.x + threadIdx.x;
    if (idx >= B_ * T_ * (D_ / 4)) return;
    int row  = idx / (D_ / 4);
    int col4 = idx % (D_ / 4);
    float4 v = Hf[idx];
    uint2* dst = reinterpret_cast<uint2*>(g_hcat + (size_t)row * D2_ + D_ + col4 * 4);
    *dst = make_uint2(pack_f16(v.x, v.y), pack_f16(v.z, v.w));
}

// ---------------- fp16 GEMM core: C[M,N] = A[M,K] @ W[N,K]^T + bias ---------
// Block 128x128, BK=64 halves (128 B/row), 128 threads = 4 warps (2m x 2n),
// warp tile 64x64, 2-stage cp.async. Pitch 36 uints -> conflict-free frags.
// OUT: 0 = fp32 to C, 1 = fp16 packed to C (ldc in halves), 2 = fp16 to g_Vt.
#define PU    36
#define TILEU (128 * PU)
#define GEMM_SMEM (2 * 2 * TILEU * 4)             // 73728 B

template <int OUT>
__device__ __forceinline__ void gemm_core_f16(
    const uint32_t* __restrict__ A, int ldau,      // uints per A row
    const uint32_t* __restrict__ W, int Kdim,      // Kdim in halves
    const float* __restrict__ bias,
    void* __restrict__ Cv, int ldc,
    size_t mBase, int nBase, uint32_t* sm)
{
    const uint32_t sm_base = smem_u32(sm);
    const int tid  = threadIdx.x;
    const int lane = tid & 31;
    const int warp = tid >> 5;
    const int g    = lane >> 2;
    const int tq   = lane & 3;
    const int wm   = warp & 1;
    const int wn   = warp >> 1;

    const uint32_t* Ap = A + mBase * ldau;
    const int ldwu = Kdim >> 1;
    const uint32_t* Wp = W + (size_t)nBase * ldwu;

    float acc[4][8][4];
    #pragma unroll
    for (int mt = 0; mt < 4; mt++)
        #pragma unroll
        for (int nt = 0; nt < 8; nt++)
            #pragma unroll
            for (int e = 0; e < 4; e++) acc[mt][nt][e] = 0.f;

    const int mrow = tid >> 3;          // 0..15 (+16j)
    const int kchk = (tid & 7) << 2;    // uint offset of 16B chunk

    auto load_tile = [&](int s, int k0u) {
        uint32_t dA = sm_base + (uint32_t)(s * 2 * TILEU) * 4;
        uint32_t dB = dA + TILEU * 4;
        #pragma unroll
        for (int j = 0; j < 8; j++) {
            int m = mrow + 16 * j;
            cp_async16(dA + (uint32_t)(m * PU + kchk) * 4,
                       Ap + (size_t)m * ldau + k0u + kchk);
            cp_async16(dB + (uint32_t)(m * PU + kchk) * 4,
                       Wp + (size_t)m * ldwu + k0u + kchk);
        }
        asm volatile("cp.async.commit_group;" ::: "memory");
    };

    const int niter = Kdim >> 6;        // BK = 64 halves = 32 uints
    load_tile(0, 0);

    for (int it = 0; it < niter; it++) {
        if (it + 1 < niter) {
            load_tile((it + 1) & 1, (it + 1) << 5);
            asm volatile("cp.async.wait_group 1;" ::: "memory");
        } else {
            asm volatile("cp.async.wait_group 0;" ::: "memory");
        }
        __syncthreads();

        const uint32_t* sA = sm + (it & 1) * 2 * TILEU;
        const uint32_t* sB = sA + TILEU;

        #pragma unroll
        for (int s = 0; s < 4; s++) {          // 4 k-steps of 16 halves
            const int k = 8 * s;
            uint32_t af[4][4], bf[8][2];
            #pragma unroll
            for (int mt = 0; mt < 4; mt++) {
                int m0 = wm * 64 + mt * 16 + g;
                af[mt][0] = sA[m0 * PU + k + tq];
                af[mt][1] = sA[(m0 + 8) * PU + k + tq];
                af[mt][2] = sA[m0 * PU + k + tq + 4];
                af[mt][3] = sA[(m0 + 8) * PU + k + tq + 4];
            }
            #pragma unroll
            for (int nt = 0; nt < 8; nt++) {
                int n0 = wn * 64 + nt * 8 + g;
                bf[nt][0] = sB[n0 * PU + k + tq];
                bf[nt][1] = sB[n0 * PU + k + tq + 4];
            }
            #pragma unroll
            for (int mt = 0; mt < 4; mt++)
                #pragma unroll
                for (int nt = 0; nt < 8; nt++)
                    mma_f16(acc[mt][nt], af[mt], bf[nt]);
        }
        __syncthreads();
    }

    #pragma unroll
    for (int nt = 0; nt < 8; nt++) {
        int col = nBase + wn * 64 + nt * 8 + 2 * tq;
        float2 bv = *reinterpret_cast<const float2*>(&bias[col]);
        #pragma unroll
        for (int mt = 0; mt < 4; mt++) {
            size_t row = mBase + wm * 64 + mt * 16 + g;
            float v00 = acc[mt][nt][0] + bv.x, v01 = acc[mt][nt][1] + bv.y;
            float v10 = acc[mt][nt][2] + bv.x, v11 = acc[mt][nt][3] + bv.y;
            if (OUT == 2) {
                int bb = (int)(row >> 11);
                int t  = (int)(row & 2047);
                __half* base = g_Vt + ((size_t)bb * D_ + col) * T_ + t;
                base[0]      = __float2half(v00);
                base[T_]     = __float2half(v01);
                base[8]      = __float2half(v10);
                base[T_ + 8] = __float2half(v11);
            } else if (OUT == 1) {
                uint32_t* Ch = reinterpret_cast<uint32_t*>(Cv);
                Ch[row * (ldc >> 1) + (col >> 1)]       = pack_f16(v00, v01);
                Ch[(row + 8) * (ldc >> 1) + (col >> 1)] = pack_f16(v10, v11);
            } else {
                float* C = reinterpret_cast<float*>(Cv);
                *reinterpret_cast<float2*>(&C[row * ldc + col])       = make_float2(v00, v01);
                *reinterpret_cast<float2*>(&C[(row + 8) * ldc + col]) = make_float2(v10, v11);
            }
        }
    }
}

// ---- fused Q/K/V/bias projections: one launch, per-block routing -----------
__global__ void __launch_bounds__(128) proj_fused_kernel(
    const float* __restrict__ bq, const float* __restrict__ bk,
    const float* __restrict__ bv, const float* __restrict__ bg)
{
    extern __shared__ uint32_t sm[];
    const int bx = blockIdx.x;
    const size_t mB = (size_t)blockIdx.y * 128;
    const uint32_t* hcat = reinterpret_cast<const uint32_t*>(g_hcat);
    if (bx < 8)
        gemm_core_f16<1>(hcat, D2_ / 2, (const uint32_t*)g_Wq, D2_, bq,
                         g_Q, D_, mB, bx * 128, sm);
    else if (bx < 16)
        gemm_core_f16<1>(hcat, D2_ / 2, (const uint32_t*)g_Wk, D2_, bk,
                         g_K, D_, mB, (bx - 8) * 128, sm);
    else if (bx < 24)
        gemm_core_f16<2>(hcat, D2_ / 2, (const uint32_t*)g_Wv, D_, bv,
                         nullptr, 0, mB, (bx - 16) * 128, sm);
    else
        gemm_core_f16<0>((const uint32_t*)g_Gm, DM_ / 2, (const uint32_t*)g_Wg, DM_, bg,
                         g_bias, T_, mB, (bx - 24) * 128, sm);
}

// ---- output projection: out = O @ Wo^T + bo (fp16 in, fp32 out) ------------
__global__ void __launch_bounds__(128) out_proj_kernel(
    const float* __restrict__ bo, float* __restrict__ out)
{
    extern __shared__ uint32_t sm[];
    gemm_core_f16<0>((const uint32_t*)g_O, D_ / 2, (const uint32_t*)g_Wo, D_, bo,
                     out, D_, (size_t)blockIdx.y * 128, blockIdx.x * 128, sm);
}

// ---------------- flash attention: all-fp16 mma (round-14, O -> fp16) -------
#define KLD  36
#define VLD  36
#define PLD  36
#define KWU  (64 * KLD)
#define VWU  (64 * VLD)
#define STGU (KWU + VWU)
#define PQW  (128 * PLD)
#define ATTN_SMEM ((2 * STGU + PQW) * (int)sizeof(uint32_t))   // 55296 B

__global__ void __launch_bounds__(128, 1) attn_f16_kernel() {
    extern __shared__ uint32_t smu[];
    uint32_t* P = smu + 2 * STGU;

    const int tid  = threadIdx.x;
    const int lane = tid & 31;
    const int warp = tid >> 5;
    const int g    = lane >> 2;
    const int tq   = lane & 3;
    const int b    = blockIdx.z;
    const int h    = blockIdx.y;
    const int q0   = blockIdx.x * 128;

    const uint32_t smb = smem_u32(smu);

    const uint32_t* __restrict__ Qg =
        reinterpret_cast<const uint32_t*>(g_Q) + ((size_t)b * T_ * D_ + (size_t)h * DK_) / 2;
    const uint32_t* __restrict__ Kg =
        reinterpret_cast<const uint32_t*>(g_K) + ((size_t)b * T_ * D_ + (size_t)h * DK_) / 2;
    const __half*   __restrict__ Vtg =
        g_Vt + ((size_t)b * D_ + (size_t)h * DK_) * T_;
    const float*    __restrict__ Bg = g_bias + ((size_t)b * T_ + q0) * T_;

    const int ldq = D_ / 2;

    auto load_kv = [&](int st, int k0) {
        uint32_t dK = smb + (uint32_t)(st * STGU) * 4;
        uint32_t dV = dK + KWU * 4;
        #pragma unroll
        for (int j = 0; j < 4; j++) {
            int i = tid + 128 * j;
            int r = i >> 3, c = i & 7;
            cp_async16(dK + (uint32_t)(r * KLD + 4 * c) * 4,
                       Kg + (size_t)(k0 + r) * ldq + 4 * c);
        }
        #pragma unroll
        for (int j = 0; j < 4; j++) {
            int i = tid + 128 * j;
            int r = i >> 3, c = i & 7;
            cp_async16(dV + (uint32_t)(r * VLD + 4 * c) * 4,
                       Vtg + (size_t)r * T_ + k0 + 8 * c);
        }
        asm volatile("cp.async.commit_group;" ::: "memory");
    };

    load_kv(0, 0);

    #pragma unroll
    for (int i = tid; i < 128 * 8; i += 128) {
        int r = i >> 3, c4 = (i & 7) << 2;
        uint4 v = *reinterpret_cast<const uint4*>(&Qg[(size_t)(q0 + r) * ldq + c4]);
        *reinterpret_cast<uint4*>(&P[r * PLD + c4]) = v;
    }
    __syncthreads();

    uint32_t qa0[4][4], qa1[4][4];
    {
        const uint32_t* Q0 = P + (warp * 32 + g) * PLD;
        const uint32_t* Q1 = P + (warp * 32 + 16 + g) * PLD;
        #pragma unroll
        for (int s = 0; s < 4; s++) {
            qa0[s][0] = Q0[8 * s + tq];
            qa0[s][1] = Q0[8 * PLD + 8 * s + tq];
            qa0[s][2] = Q0[8 * s + tq + 4];
            qa0[s][3] = Q0[8 * PLD + 8 * s + tq + 4];
            qa1[s][0] = Q1[8 * s + tq];
            qa1[s][1] = Q1[8 * PLD + 8 * s + tq];
            qa1[s][2] = Q1[8 * s + tq + 4];
            qa1[s][3] = Q1[8 * PLD + 8 * s + tq + 4];
        }
    }
    __syncthreads();

    float o0[8][4], o1[8][4];
    #pragma unroll
    for (int nt = 0; nt < 8; nt++)
        #pragma unroll
        for (int e = 0; e < 4; e++) { o0[nt][e] = 0.f; o1[nt][e] = 0.f; }
    float rs[4] = {0.f, 0.f, 0.f, 0.f};

    uint32_t* Pw = P + warp * 32 * PLD;
    const int niter = T_ / 64;

    for (int it = 0; it < niter; it++) {
        const int k0 = it * 64;
        if (it + 1 < niter) {
            load_kv((it + 1) & 1, k0 + 64);
            asm volatile("cp.async.wait_group 1;" ::: "memory");
        } else {
            asm volatile("cp.async.wait_group 0;" ::: "memory");
        }
        __syncthreads();

        const uint32_t* sK  = smu + (it & 1) * STGU;
        const uint32_t* sVt = sK + KWU;
        const float*    B0  = Bg + (size_t)(warp * 32 + g) * T_ + k0;

        #pragma unroll
        for (int ntp = 0; ntp < 4; ntp++) {
            const int ntA = 2 * ntp, ntB = 2 * ntp + 1;
            const int cbA = ntA * 8 + 2 * tq, cbB = ntB * 8 + 2 * tq;

            float2 bA00 = *reinterpret_cast<const float2*>(&B0[cbA]);
            float2 bA01 = *reinterpret_cast<const float2*>(&B0[8  * T_ + cbA]);
            float2 bA10 = *reinterpret_cast<const float2*>(&B0[16 * T_ + cbA]);
            float2 bA11 = *reinterpret_cast<const float2*>(&B0[24 * T_ + cbA]);
            float2 bB00 = *reinterpret_cast<const float2*>(&B0[cbB]);
            float2 bB01 = *reinterpret_cast<const float2*>(&B0[8  * T_ + cbB]);
            float2 bB10 = *reinterpret_cast<const float2*>(&B0[16 * T_ + cbB]);
            float2 bB11 = *reinterpret_cast<const float2*>(&B0[24 * T_ + cbB]);

            float sA0[4] = {0.f,0.f,0.f,0.f}, sA1[4] = {0.f,0.f,0.f,0.f};
            float sB0[4] = {0.f,0.f,0.f,0.f}, sB1[4] = {0.f,0.f,0.f,0.f};
            #pragma unroll
            for (int s = 0; s < 4; s++) {
                const uint32_t* KrA = sK + (ntA * 8 + g) * KLD + 8 * s + tq;
                const uint32_t* KrB = sK + (ntB * 8 + g) * KLD + 8 * s + tq;
                uint32_t bbA[2] = { KrA[0], KrA[4] };
                uint32_t bbB[2] = { KrB[0], KrB[4] };
                mma_f16(sA0, qa0[s], bbA);
                mma_f16(sA1, qa1[s], bbA);
                mma_f16(sB0, qa0[s], bbB);
                mma_f16(sB1, qa1[s], bbB);
            }

            float pA00 = __expf(fmaf(sA0[0], 0.125f, bA00.x));
            float pA01 = __expf(fmaf(sA0[1], 0.125f, bA00.y));
            float pA02 = __expf(fmaf(sA0[2], 0.125f, bA01.x));
            float pA03 = __expf(fmaf(sA0[3], 0.125f, bA01.y));
            float pA10 = __expf(fmaf(sA1[0], 0.125f, bA10.x));
            float pA11 = __expf(fmaf(sA1[1], 0.125f, bA10.y));
            float pA12 = __expf(fmaf(sA1[2], 0.125f, bA11.x));
            float pA13 = __expf(fmaf(sA1[3], 0.125f, bA11.y));
            float pB00 = __expf(fmaf(sB0[0], 0.125f, bB00.x));
            float pB01 = __expf(fmaf(sB0[1], 0.125f, bB00.y));
            float pB02 = __expf(fmaf(sB0[2], 0.125f, bB01.x));
            float pB03 = __expf(fmaf(sB0[3], 0.125f, bB01.y));
            float pB10 = __expf(fmaf(sB1[0], 0.125f, bB10.x));
            float pB11 = __expf(fmaf(sB1[1], 0.125f, bB10.y));
            float pB12 = __expf(fmaf(sB1[2], 0.125f, bB11.x));
            float pB13 = __expf(fmaf(sB1[3], 0.125f, bB11.y));

            rs[0] += pA00 + pA01 + pB00 + pB01;
            rs[1] += pA02 + pA03 + pB02 + pB03;
            rs[2] += pA10 + pA11 + pB10 + pB11;
            rs[3] += pA12 + pA13 + pB12 + pB13;

            Pw[g * PLD        + ntA * 4 + tq] = pack_f16(pA00, pA01);
            Pw[(g + 8) * PLD  + ntA * 4 + tq] = pack_f16(pA02, pA03);
            Pw[(g + 16) * PLD + ntA * 4 + tq] = pack_f16(pA10, pA11);
            Pw[(g + 24) * PLD + ntA * 4 + tq] = pack_f16(pA12, pA13);
            Pw[g * PLD        + ntB * 4 + tq] = pack_f16(pB00, pB01);
            Pw[(g + 8) * PLD  + ntB * 4 + tq] = pack_f16(pB02, pB03);
            Pw[(g + 16) * PLD + ntB * 4 + tq] = pack_f16(pB10, pB11);
            Pw[(g + 24) * PLD + ntB * 4 + tq] = pack_f16(pB12, pB13);
        }
        __syncwarp();

        #pragma unroll
        for (int s = 0; s < 4; s++) {
            uint32_t pa0[4], pa1[4];
            pa0[0] = Pw[g * PLD + 8 * s + tq];
            pa0[1] = Pw[(g + 8) * PLD + 8 * s + tq];
            pa0[2] = Pw[g * PLD + 8 * s + tq + 4];
            pa0[3] = Pw[(g + 8) * PLD + 8 * s + tq + 4];
            pa1[0] = Pw[(g + 16) * PLD + 8 * s + tq];
            pa1[1] = Pw[(g + 24) * PLD + 8 * s + tq];
            pa1[2] = Pw[(g + 16) * PLD + 8 * s + tq + 4];
            pa1[3] = Pw[(g + 24) * PLD + 8 * s + tq + 4];
            #pragma unroll
            for (int nt = 0; nt < 8; nt++) {
                uint32_t bb[2];
                bb[0] = sVt[(nt * 8 + g) * VLD + 8 * s + tq];
                bb[1] = sVt[(nt * 8 + g) * VLD + 8 * s + tq + 4];
                mma_f16(o0[nt], pa0, bb);
                mma_f16(o1[nt], pa1, bb);
            }
        }
        __syncthreads();
    }

    #pragma unroll
    for (int e = 0; e < 4; e++) {
        rs[e] += __shfl_xor_sync(0xffffffffu, rs[e], 1);
        rs[e] += __shfl_xor_sync(0xffffffffu, rs[e], 2);
    }
    float inv0 = 1.0f / rs[0], inv1 = 1.0f / rs[1];
    float inv2 = 1.0f / rs[2], inv3 = 1.0f / rs[3];

    // O epilogue: fp16 packed (cols 2tq,2tq+1 are one uint)
    uint32_t* Og = reinterpret_cast<uint32_t*>(g_O) +
                   ((size_t)b * T_ * D_ + (size_t)h * DK_) / 2;
    size_t r0 = (size_t)q0 + warp * 32 + g;
    const int ldo = D_ / 2;
    #pragma unroll
    for (int nt = 0; nt < 8; nt++) {
        int cu = nt * 4 + tq;
        Og[r0 * ldo + cu]        = pack_f16(o0[nt][0] * inv0, o0[nt][1] * inv0);
        Og[(r0 + 8) * ldo + cu]  = pack_f16(o0[nt][2] * inv1, o0[nt][3] * inv1);
        Og[(r0 + 16) * ldo + cu] = pack_f16(o1[nt][0] * inv2, o1[nt][1] * inv2);
        Og[(r0 + 24) * ldo + cu] = pack_f16(o1[nt][2] * inv3, o1[nt][3] * inv3);
    }
}

// ---------------- launch ----------------------------------------------------
extern "C" void kernel_launch(void* const* d_in, const int* in_sizes, int n_in,
                              void* d_out, int out_size) {
    const float* Hx = (const float*)d_in[0];
    const float* Hf = (const float*)d_in[1];
    const float* Gm = (const float*)d_in[2];
    const float* Wg = (const float*)d_in[3];
    const float* bg = (const float*)d_in[4];
    const float* Wq = (const float*)d_in[5];
    const float* bq = (const float*)d_in[6];
    const float* Wk = (const float*)d_in[7];
    const float* bk = (const float*)d_in[8];
    const float* Wv = (const float*)d_in[9];
    const float* bv = (const float*)d_in[10];
    const float* Wo = (const float*)d_in[11];
    const float* bo = (const float*)d_in[12];
    float* out = (float*)d_out;

    void *wq, *wk, *wv, *wo, *wg, *gm;
    cudaGetSymbolAddress(&wq, g_Wq);
    cudaGetSymbolAddress(&wk, g_Wk);
    cudaGetSymbolAddress(&wv, g_Wv);
    cudaGetSymbolAddress(&wo, g_Wo);
    cudaGetSymbolAddress(&wg, g_Wg);
    cudaGetSymbolAddress(&gm, g_Gm);

    cudaFuncSetAttribute(proj_fused_kernel,
                         cudaFuncAttributeMaxDynamicSharedMemorySize, GEMM_SMEM);
    cudaFuncSetAttribute(out_proj_kernel,
                         cudaFuncAttributeMaxDynamicSharedMemorySize, GEMM_SMEM);
    cudaFuncSetAttribute(attn_f16_kernel,
                         cudaFuncAttributeMaxDynamicSharedMemorySize, ATTN_SMEM);

    // 0) convert weights + Gm to fp16
    auto cvt = [&](const float* src, void* dst, int n) {
        int n4 = n >> 2;
        cvt_f16_kernel<<<(n4 + 255) / 256, 256>>>((const float4*)src, (uint2*)dst, n4);
    };
    cvt(Wq, wq, D_ * D2_);
    cvt(Wk, wk, D_ * D2_);
    cvt(Wv, wv, D_ * D_);
    cvt(Wo, wo, D_ * D_);
    cvt(Wg, wg, T_ * DM_);
    cvt(Gm, gm, B_ * T_ * DM_);

    // 1) build hcat = [hx | Hf] (fp16)
    transpose_hx_kernel<<<dim3(T_ / 32, D_ / 32, B_), dim3(32, 8)>>>(Hx);
    copy_hf_kernel<<<(B_ * T_ * (D_ / 4) + 255) / 256, 256>>>((const float4*)Hf);

    // 2) all projections in ONE launch (Q/K fp16, V fp16 transposed, bias fp32)
    proj_fused_kernel<<<dim3(40, 32), 128, GEMM_SMEM>>>(bq, bk, bv, bg);

    // 3) attention (all-fp16 tensor path, O -> fp16)
    attn_f16_kernel<<<dim3(T_ / 128, H_, B_), 128, ATTN_SMEM>>>();

    // 4) output projection (fp16 in, fp32 out)
    out_proj_kernel<<<dim3(D_ / 128, 32), 128, GEMM_SMEM>>>(bo, out);
}

// round 16
// speedup vs baseline: 2.2693x; 1.0771x over previous
#include <cuda_runtime.h>
#include <cuda_fp16.h>
#include <math_constants.h>
#include <cstdint>

#define B_   2
#define T_   2048
#define D_   1024
#define H_   16
#define DK_  64
#define DM_  256
#define D2_  2048
#define LOG2E 1.4426950408889634f

// ---------------- scratch (device globals; no allocation allowed) ----------
__device__ __half g_hcat[(size_t)B_ * T_ * D2_];
__device__ __half g_Q  [(size_t)B_ * T_ * D_];
__device__ __half g_K  [(size_t)B_ * T_ * D_];
__device__ __half g_Vt [(size_t)B_ * D_ * T_];
__device__ __half g_O  [(size_t)B_ * T_ * D_];
__device__ float  g_bias[(size_t)B_ * T_ * T_];   // pre-scaled by log2(e)
__device__ __half g_Wq[(size_t)D_ * D2_];
__device__ __half g_Wk[(size_t)D_ * D2_];
__device__ __half g_Wv[(size_t)D_ * D_];
__device__ __half g_Wo[(size_t)D_ * D_];
__device__ __half g_Wg[(size_t)T_ * DM_];
__device__ __half g_Gm[(size_t)B_ * T_ * DM_];

// ---------------- helpers ----------------------------------------------------
__device__ __forceinline__ uint32_t pack_f16(float lo, float hi) {
    uint32_t u; asm("cvt.rn.f16x2.f32 %0, %1, %2;" : "=r"(u) : "f"(hi), "f"(lo)); return u;
}
__device__ __forceinline__ float ex2(float x) {
    float r; asm("ex2.approx.ftz.f32 %0, %1;" : "=f"(r) : "f"(x)); return r;
}
__device__ __forceinline__ void mma_f16(float* c, const uint32_t* a, const uint32_t* b) {
    asm volatile("mma.sync.aligned.m16n8k16.row.col.f32.f16.f16.f32 "
        "{%0,%1,%2,%3}, {%4,%5,%6,%7}, {%8,%9}, {%0,%1,%2,%3};\n"
        : "+f"(c[0]), "+f"(c[1]), "+f"(c[2]), "+f"(c[3])
        : "r"(a[0]), "r"(a[1]), "r"(a[2]), "r"(a[3]), "r"(b[0]), "r"(b[1]));
}
__device__ __forceinline__ uint32_t smem_u32(const void* p) {
    uint32_t a;
    asm("{ .reg .u64 t; cvta.to.shared.u64 t, %1; cvt.u32.u64 %0, t; }" : "=r"(a) : "l"(p));
    return a;
}
__device__ __forceinline__ void cp_async16(uint32_t dst, const void* src) {
    asm volatile("cp.async.cg.shared.global [%0], [%1], 16;"
                 :: "r"(dst), "l"(src) : "memory");
}

// ---------------- fp32 -> fp16 conversion (weights, Gm) ---------------------
__global__ void cvt_f16_kernel(const float4* __restrict__ src,
                               uint2* __restrict__ dst, int n4) {
    int i = blockIdx.x * blockDim.x + threadIdx.x;
    if (i >= n4) return;
    float4 v = src[i];
    dst[i] = make_uint2(pack_f16(v.x, v.y), pack_f16(v.z, v.w));
}

// ---------------- hx transpose: Hx (B,D,T,1) -> g_hcat[:, 0:D] (fp16) -------
__global__ void transpose_hx_kernel(const float* __restrict__ Hx) {
    __shared__ float tile[32][33];
    int b  = blockIdx.z;
    int d0 = blockIdx.y * 32;
    int t0 = blockIdx.x * 32;
    #pragma unroll
    for (int yy = threadIdx.y; yy < 32; yy += 8)
        tile[yy][threadIdx.x] = Hx[((size_t)(b * D_ + d0 + yy)) * T_ + t0 + threadIdx.x];
    __syncthreads();
    #pragma unroll
    for (int yy = threadIdx.y; yy < 32; yy += 8)
        g_hcat[((size_t)(b * T_ + t0 + yy)) * D2_ + d0 + threadIdx.x] =
            __float2half(tile[threadIdx.x][yy]);
}

__global__ void copy_hf_kernel(const float4* __restrict__ Hf) {
    int idx = blockIdx.x * blockDim.x + threadIdx.x;
    if (idx >= B_ * T_ * (D_ / 4)) return;
    int row  = idx / (D_ / 4);
    int col4 = idx % (D_ / 4);
    float4 v = Hf[idx];
    uint2* dst = reinterpret_cast<uint2*>(g_hcat + (size_t)row * D2_ + D_ + col4 * 4);
    *dst = make_uint2(pack_f16(v.x, v.y), pack_f16(v.z, v.w));
}

// ---------------- fp16 GEMM core (round-15 proven config) -------------------
// OUT: 0 = fp32*(oscale) to C, 1 = fp16 packed to C, 2 = fp16 to g_Vt.
#define PU    36
#define TILEU (128 * PU)
#define GEMM_SMEM (2 * 2 * TILEU * 4)             // 73728 B

template <int OUT>
__device__ __forceinline__ void gemm_core_f16(
    const uint32_t* __restrict__ A, int ldau,
    const uint32_t* __restrict__ W, int Kdim,
    const float* __restrict__ bias,
    void* __restrict__ Cv, int ldc,
    size_t mBase, int nBase, uint32_t* sm, float oscale)
{
    const uint32_t sm_base = smem_u32(sm);
    const int tid  = threadIdx.x;
    const int lane = tid & 31;
    const int warp = tid >> 5;
    const int g    = lane >> 2;
    const int tq   = lane & 3;
    const int wm   = warp & 1;
    const int wn   = warp >> 1;

    const uint32_t* Ap = A + mBase * ldau;
    const int ldwu = Kdim >> 1;
    const uint32_t* Wp = W + (size_t)nBase * ldwu;

    float acc[4][8][4];
    #pragma unroll
    for (int mt = 0; mt < 4; mt++)
        #pragma unroll
        for (int nt = 0; nt < 8; nt++)
            #pragma unroll
            for (int e = 0; e < 4; e++) acc[mt][nt][e] = 0.f;

    const int mrow = tid >> 3;
    const int kchk = (tid & 7) << 2;

    auto load_tile = [&](int s, int k0u) {
        uint32_t dA = sm_base + (uint32_t)(s * 2 * TILEU) * 4;
        uint32_t dB = dA + TILEU * 4;
        #pragma unroll
        for (int j = 0; j < 8; j++) {
            int m = mrow + 16 * j;
            cp_async16(dA + (uint32_t)(m * PU + kchk) * 4,
                       Ap + (size_t)m * ldau + k0u + kchk);
            cp_async16(dB + (uint32_t)(m * PU + kchk) * 4,
                       Wp + (size_t)m * ldwu + k0u + kchk);
        }
        asm volatile("cp.async.commit_group;" ::: "memory");
    };

    const int niter = Kdim >> 6;
    load_tile(0, 0);

    for (int it = 0; it < niter; it++) {
        if (it + 1 < niter) {
            load_tile((it + 1) & 1, (it + 1) << 5);
            asm volatile("cp.async.wait_group 1;" ::: "memory");
        } else {
            asm volatile("cp.async.wait_group 0;" ::: "memory");
        }
        __syncthreads();

        const uint32_t* sA = sm + (it & 1) * 2 * TILEU;
        const uint32_t* sB = sA + TILEU;

        #pragma unroll
        for (int s = 0; s < 4; s++) {
            const int k = 8 * s;
            uint32_t af[4][4], bf[8][2];
            #pragma unroll
            for (int mt = 0; mt < 4; mt++) {
                int m0 = wm * 64 + mt * 16 + g;
                af[mt][0] = sA[m0 * PU + k + tq];
                af[mt][1] = sA[(m0 + 8) * PU + k + tq];
                af[mt][2] = sA[m0 * PU + k + tq + 4];
                af[mt][3] = sA[(m0 + 8) * PU + k + tq + 4];
            }
            #pragma unroll
            for (int nt = 0; nt < 8; nt++) {
                int n0 = wn * 64 + nt * 8 + g;
                bf[nt][0] = sB[n0 * PU + k + tq];
                bf[nt][1] = sB[n0 * PU + k + tq + 4];
            }
            #pragma unroll
            for (int mt = 0; mt < 4; mt++)
                #pragma unroll
                for (int nt = 0; nt < 8; nt++)
                    mma_f16(acc[mt][nt], af[mt], bf[nt]);
        }
        __syncthreads();
    }

    #pragma unroll
    for (int nt = 0; nt < 8; nt++) {
        int col = nBase + wn * 64 + nt * 8 + 2 * tq;
        float2 bv = *reinterpret_cast<const float2*>(&bias[col]);
        #pragma unroll
        for (int mt = 0; mt < 4; mt++) {
            size_t row = mBase + wm * 64 + mt * 16 + g;
            float v00 = acc[mt][nt][0] + bv.x, v01 = acc[mt][nt][1] + bv.y;
            float v10 = acc[mt][nt][2] + bv.x, v11 = acc[mt][nt][3] + bv.y;
            if (OUT == 2) {
                int bb = (int)(row >> 11);
                int t  = (int)(row & 2047);
                __half* base = g_Vt + ((size_t)bb * D_ + col) * T_ + t;
                base[0]      = __float2half(v00);
                base[T_]     = __float2half(v01);
                base[8]      = __float2half(v10);
                base[T_ + 8] = __float2half(v11);
            } else if (OUT == 1) {
                uint32_t* Ch = reinterpret_cast<uint32_t*>(Cv);
                Ch[row * (ldc >> 1) + (col >> 1)]       = pack_f16(v00, v01);
                Ch[(row + 8) * (ldc >> 1) + (col >> 1)] = pack_f16(v10, v11);
            } else {
                float* C = reinterpret_cast<float*>(Cv);
                *reinterpret_cast<float2*>(&C[row * ldc + col]) =
                    make_float2(v00 * oscale, v01 * oscale);
                *reinterpret_cast<float2*>(&C[(row + 8) * ldc + col]) =
                    make_float2(v10 * oscale, v11 * oscale);
            }
        }
    }
}

// ---- fused Q/K/V/bias projections (bias pre-scaled by log2e) ---------------
__global__ void __launch_bounds__(128) proj_fused_kernel(
    const float* __restrict__ bq, const float* __restrict__ bk,
    const float* __restrict__ bv, const float* __restrict__ bg)
{
    extern __shared__ uint32_t sm[];
    const int bx = blockIdx.x;
    const size_t mB = (size_t)blockIdx.y * 128;
    const uint32_t* hcat = reinterpret_cast<const uint32_t*>(g_hcat);
    if (bx < 8)
        gemm_core_f16<1>(hcat, D2_ / 2, (const uint32_t*)g_Wq, D2_, bq,
                         g_Q, D_, mB, bx * 128, sm, 1.f);
    else if (bx < 16)
        gemm_core_f16<1>(hcat, D2_ / 2, (const uint32_t*)g_Wk, D2_, bk,
                         g_K, D_, mB, (bx - 8) * 128, sm, 1.f);
    else if (bx < 24)
        gemm_core_f16<2>(hcat, D2_ / 2, (const uint32_t*)g_Wv, D_, bv,
                         nullptr, 0, mB, (bx - 16) * 128, sm, 1.f);
    else
        gemm_core_f16<0>((const uint32_t*)g_Gm, DM_ / 2, (const uint32_t*)g_Wg, DM_, bg,
                         g_bias, T_, mB, (bx - 24) * 128, sm, LOG2E);
}

__global__ void __launch_bounds__(128) out_proj_kernel(
    const float* __restrict__ bo, float* __restrict__ out)
{
    extern __shared__ uint32_t sm[];
    gemm_core_f16<0>((const uint32_t*)g_O, D_ / 2, (const uint32_t*)g_Wo, D_, bo,
                     out, D_, (size_t)blockIdx.y * 128, blockIdx.x * 128, sm, 1.f);
}

// ---------------- flash attention: fused S->P->PV in registers --------------
// The m16n8k16 C-fragment of the S mma IS the A-fragment of the PV mma for
// the matching 16-token k-step, so P never touches smem. Q is staged into the
// stage-1 K/V buffer (overwritten by load_kv(1) => forced register residency).
#define KLD  36
#define VLD  36
#define KWU  (64 * KLD)
#define VWU  (64 * VLD)
#define STGU (KWU + VWU)              // 4608 uints per stage
#define ATTN_SMEM (2 * STGU * (int)sizeof(uint32_t))   // 36864 B

__global__ void __launch_bounds__(128, 1) attn_f16_kernel() {
    extern __shared__ uint32_t smu[];
    uint32_t* Qst = smu + STGU;       // Q staging in stage-1 buffer (clobbered)

    const int tid  = threadIdx.x;
    const int lane = tid & 31;
    const int warp = tid >> 5;
    const int g    = lane >> 2;
    const int tq   = lane & 3;
    const int b    = blockIdx.z;
    const int h    = blockIdx.y;
    const int q0   = blockIdx.x * 128;

    const uint32_t smb = smem_u32(smu);

    const uint32_t* __restrict__ Qg =
        reinterpret_cast<const uint32_t*>(g_Q) + ((size_t)b * T_ * D_ + (size_t)h * DK_) / 2;
    const uint32_t* __restrict__ Kg =
        reinterpret_cast<const uint32_t*>(g_K) + ((size_t)b * T_ * D_ + (size_t)h * DK_) / 2;
    const __half*   __restrict__ Vtg =
        g_Vt + ((size_t)b * D_ + (size_t)h * DK_) * T_;
    const float*    __restrict__ Bg = g_bias + ((size_t)b * T_ + q0) * T_;

    const int ldq = D_ / 2;
    const float SC = 0.125f * LOG2E;   // bias already carries log2e

    auto load_kv = [&](int st, int k0) {
        uint32_t dK = smb + (uint32_t)(st * STGU) * 4;
        uint32_t dV = dK + KWU * 4;
        #pragma unroll
        for (int j = 0; j < 4; j++) {
            int i = tid + 128 * j;
            int r = i >> 3, c = i & 7;
            cp_async16(dK + (uint32_t)(r * KLD + 4 * c) * 4,
                       Kg + (size_t)(k0 + r) * ldq + 4 * c);
        }
        #pragma unroll
        for (int j = 0; j < 4; j++) {
            int i = tid + 128 * j;
            int r = i >> 3, c = i & 7;
            cp_async16(dV + (uint32_t)(r * VLD + 4 * c) * 4,
                       Vtg + (size_t)r * T_ + k0 + 8 * c);
        }
        asm volatile("cp.async.commit_group;" ::: "memory");
    };

    load_kv(0, 0);

    // stage Q (128 rows x 32 uints) into the stage-1 buffer, pitch KLD=36
    #pragma unroll
    for (int i = tid; i < 128 * 8; i += 128) {
        int r = i >> 3, c4 = (i & 7) << 2;
        uint4 v = *reinterpret_cast<const uint4*>(&Qg[(size_t)(q0 + r) * ldq + c4]);
        *reinterpret_cast<uint4*>(&Qst[r * 36 + c4]) = v;
    }
    __syncthreads();

    // Q fragments -> registers (stage-1 buffer is clobbered by load_kv below)
    uint32_t qa0[4][4], qa1[4][4];
    {
        const uint32_t* Q0 = Qst + (warp * 32 + g) * 36;
        const uint32_t* Q1 = Qst + (warp * 32 + 16 + g) * 36;
        #pragma unroll
        for (int s = 0; s < 4; s++) {
            qa0[s][0] = Q0[8 * s + tq];
            qa0[s][1] = Q0[8 * 36 + 8 * s + tq];
            qa0[s][2] = Q0[8 * s + tq + 4];
            qa0[s][3] = Q0[8 * 36 + 8 * s + tq + 4];
            qa1[s][0] = Q1[8 * s + tq];
            qa1[s][1] = Q1[8 * 36 + 8 * s + tq];
            qa1[s][2] = Q1[8 * s + tq + 4];
            qa1[s][3] = Q1[8 * 36 + 8 * s + tq + 4];
        }
    }
    __syncthreads();

    float o0[8][4], o1[8][4];
    #pragma unroll
    for (int nt = 0; nt < 8; nt++)
        #pragma unroll
        for (int e = 0; e < 4; e++) { o0[nt][e] = 0.f; o1[nt][e] = 0.f; }
    float rs[4] = {0.f, 0.f, 0.f, 0.f};

    const int niter = T_ / 64;

    for (int it = 0; it < niter; it++) {
        const int k0 = it * 64;
        if (it + 1 < niter) {
            load_kv((it + 1) & 1, k0 + 64);
            asm volatile("cp.async.wait_group 1;" ::: "memory");
        } else {
            asm volatile("cp.async.wait_group 0;" ::: "memory");
        }
        __syncthreads();

        const uint32_t* sK  = smu + (it & 1) * STGU;
        const uint32_t* sVt = sK + KWU;
        const float*    B0  = Bg + (size_t)(warp * 32 + g) * T_ + k0;

        // fused: S (k-step pair) -> exp2 -> PV (same k-step), all in registers
        #pragma unroll
        for (int ntp = 0; ntp < 4; ntp++) {
            const int ntA = 2 * ntp, ntB = 2 * ntp + 1;
            const int cbA = ntA * 8 + 2 * tq, cbB = ntB * 8 + 2 * tq;

            float2 bA00 = *reinterpret_cast<const float2*>(&B0[cbA]);
            float2 bA01 = *reinterpret_cast<const float2*>(&B0[8  * T_ + cbA]);
            float2 bA10 = *reinterpret_cast<const float2*>(&B0[16 * T_ + cbA]);
            float2 bA11 = *reinterpret_cast<const float2*>(&B0[24 * T_ + cbA]);
            float2 bB00 = *reinterpret_cast<const float2*>(&B0[cbB]);
            float2 bB01 = *reinterpret_cast<const float2*>(&B0[8  * T_ + cbB]);
            float2 bB10 = *reinterpret_cast<const float2*>(&B0[16 * T_ + cbB]);
            float2 bB11 = *reinterpret_cast<const float2*>(&B0[24 * T_ + cbB]);

            float sA0[4] = {0.f,0.f,0.f,0.f}, sA1[4] = {0.f,0.f,0.f,0.f};
            float sB0[4] = {0.f,0.f,0.f,0.f}, sB1[4] = {0.f,0.f,0.f,0.f};
            #pragma unroll
            for (int s = 0; s < 4; s++) {
                const uint32_t* KrA = sK + (ntA * 8 + g) * KLD + 8 * s + tq;
                const uint32_t* KrB = sK + (ntB * 8 + g) * KLD + 8 * s + tq;
                uint32_t bbA[2] = { KrA[0], KrA[4] };
                uint32_t bbB[2] = { KrB[0], KrB[4] };
                mma_f16(sA0, qa0[s], bbA);
                mma_f16(sA1, qa1[s], bbA);
                mma_f16(sB0, qa0[s], bbB);
                mma_f16(sB1, qa1[s], bbB);
            }

            float pA00 = ex2(fmaf(sA0[0], SC, bA00.x));
            float pA01 = ex2(fmaf(sA0[1], SC, bA00.y));
            float pA02 = ex2(fmaf(sA0[2], SC, bA01.x));
            float pA03 = ex2(fmaf(sA0[3], SC, bA01.y));
            float pA10 = ex2(fmaf(sA1[0], SC, bA10.x));
            float pA11 = ex2(fmaf(sA1[1], SC, bA10.y));
            float pA12 = ex2(fmaf(sA1[2], SC, bA11.x));
            float pA13 = ex2(fmaf(sA1[3], SC, bA11.y));
            float pB00 = ex2(fmaf(sB0[0], SC, bB00.x));
            float pB01 = ex2(fmaf(sB0[1], SC, bB00.y));
            float pB02 = ex2(fmaf(sB0[2], SC, bB01.x));
            float pB03 = ex2(fmaf(sB0[3], SC, bB01.y));
            float pB10 = ex2(fmaf(sB1[0], SC, bB10.x));
            float pB11 = ex2(fmaf(sB1[1], SC, bB10.y));
            float pB12 = ex2(fmaf(sB1[2], SC, bB11.x));
            float pB13 = ex2(fmaf(sB1[3], SC, bB11.y));

            rs[0] += pA00 + pA01 + pB00 + pB01;
            rs[1] += pA02 + pA03 + pB02 + pB03;
            rs[2] += pA10 + pA11 + pB10 + pB11;
            rs[3] += pA12 + pA13 + pB12 + pB13;

            // C-fragment == PV A-fragment (tokens 16*ntp .. 16*ntp+15)
            uint32_t pa0[4], pa1[4];
            pa0[0] = pack_f16(pA00, pA01);
            pa0[1] = pack_f16(pA02, pA03);
            pa0[2] = pack_f16(pB00, pB01);
            pa0[3] = pack_f16(pB02, pB03);
            pa1[0] = pack_f16(pA10, pA11);
            pa1[1] = pack_f16(pA12, pA13);
            pa1[2] = pack_f16(pB10, pB11);
            pa1[3] = pack_f16(pB12, pB13);

            #pragma unroll
            for (int nt = 0; nt < 8; nt++) {
                uint32_t bb[2];
                bb[0] = sVt[(nt * 8 + g) * VLD + 8 * ntp + tq];
                bb[1] = sVt[(nt * 8 + g) * VLD + 8 * ntp + tq + 4];
                mma_f16(o0[nt], pa0, bb);
                mma_f16(o1[nt], pa1, bb);
            }
        }
        __syncthreads();
    }

    #pragma unroll
    for (int e = 0; e < 4; e++) {
        rs[e] += __shfl_xor_sync(0xffffffffu, rs[e], 1);
        rs[e] += __shfl_xor_sync(0xffffffffu, rs[e], 2);
    }
    float inv0 = 1.0f / rs[0], inv1 = 1.0f / rs[1];
    float inv2 = 1.0f / rs[2], inv3 = 1.0f / rs[3];

    uint32_t* Og = reinterpret_cast<uint32_t*>(g_O) +
                   ((size_t)b * T_ * D_ + (size_t)h * DK_) / 2;
    size_t r0 = (size_t)q0 + warp * 32 + g;
    const int ldo = D_ / 2;
    #pragma unroll
    for (int nt = 0; nt < 8; nt++) {
        int cu = nt * 4 + tq;
        Og[r0 * ldo + cu]        = pack_f16(o0[nt][0] * inv0, o0[nt][1] * inv0);
        Og[(r0 + 8) * ldo + cu]  = pack_f16(o0[nt][2] * inv1, o0[nt][3] * inv1);
        Og[(r0 + 16) * ldo + cu] = pack_f16(o1[nt][0] * inv2, o1[nt][1] * inv2);
        Og[(r0 + 24) * ldo + cu] = pack_f16(o1[nt][2] * inv3, o1[nt][3] * inv3);
    }
}

// ---------------- launch ----------------------------------------------------
extern "C" void kernel_launch(void* const* d_in, const int* in_sizes, int n_in,
                              void* d_out, int out_size) {
    const float* Hx = (const float*)d_in[0];
    const float* Hf = (const float*)d_in[1];
    const float* Gm = (const float*)d_in[2];
    const float* Wg = (const float*)d_in[3];
    const float* bg = (const float*)d_in[4];
    const float* Wq = (const float*)d_in[5];
    const float* bq = (const float*)d_in[6];
    const float* Wk = (const float*)d_in[7];
    const float* bk = (const float*)d_in[8];
    const float* Wv = (const float*)d_in[9];
    const float* bv = (const float*)d_in[10];
    const float* Wo = (const float*)d_in[11];
    const float* bo = (const float*)d_in[12];
    float* out = (float*)d_out;

    void *wq, *wk, *wv, *wo, *wg, *gm;
    cudaGetSymbolAddress(&wq, g_Wq);
    cudaGetSymbolAddress(&wk, g_Wk);
    cudaGetSymbolAddress(&wv, g_Wv);
    cudaGetSymbolAddress(&wo, g_Wo);
    cudaGetSymbolAddress(&wg, g_Wg);
    cudaGetSymbolAddress(&gm, g_Gm);

    cudaFuncSetAttribute(proj_fused_kernel,
                         cudaFuncAttributeMaxDynamicSharedMemorySize, GEMM_SMEM);
    cudaFuncSetAttribute(out_proj_kernel,
                         cudaFuncAttributeMaxDynamicSharedMemorySize, GEMM_SMEM);
    cudaFuncSetAttribute(attn_f16_kernel,
                         cudaFuncAttributeMaxDynamicSharedMemorySize, ATTN_SMEM);

    auto cvt = [&](const float* src, void* dst, int n) {
        int n4 = n >> 2;
        cvt_f16_kernel<<<(n4 + 255) / 256, 256>>>((const float4*)src, (uint2*)dst, n4);
    };
    cvt(Wq, wq, D_ * D2_);
    cvt(Wk, wk, D_ * D2_);
    cvt(Wv, wv, D_ * D_);
    cvt(Wo, wo, D_ * D_);
    cvt(Wg, wg, T_ * DM_);
    cvt(Gm, gm, B_ * T_ * DM_);

    transpose_hx_kernel<<<dim3(T_ / 32, D_ / 32, B_), dim3(32, 8)>>>(Hx);
    copy_hf_kernel<<<(B_ * T_ * (D_ / 4) + 255) / 256, 256>>>((const float4*)Hf);

    proj_fused_kernel<<<dim3(40, 32), 128, GEMM_SMEM>>>(bq, bk, bv, bg);

    attn_f16_kernel<<<dim3(T_ / 128, H_, B_), 128, ATTN_SMEM>>>();

    out_proj_kernel<<<dim3(D_ / 128, 32), 128, GEMM_SMEM>>>(bo, out);
}

// round 17
// speedup vs baseline: 2.3283x; 1.0260x over previous
#include <cuda_runtime.h>
#include <cuda_fp16.h>
#include <math_constants.h>
#include <cstdint>

#define B_   2
#define T_   2048
#define D_   1024
#define H_   16
#define DK_  64
#define DM_  256
#define D2_  2048
#define LOG2E 1.4426950408889634f

// ---------------- scratch (device globals; no allocation allowed) ----------
__device__ __half g_hcat[(size_t)B_ * T_ * D2_];
__device__ __half g_Q  [(size_t)B_ * T_ * D_];
__device__ __half g_K  [(size_t)B_ * T_ * D_];
__device__ __half g_Vt [(size_t)B_ * D_ * T_];
__device__ __half g_O  [(size_t)B_ * T_ * D_];
__device__ __half g_bias[(size_t)B_ * T_ * T_];   // fp16, pre-scaled by log2(e)
__device__ __half g_Wq[(size_t)D_ * D2_];
__device__ __half g_Wk[(size_t)D_ * D2_];
__device__ __half g_Wv[(size_t)D_ * D_];
__device__ __half g_Wo[(size_t)D_ * D_];
__device__ __half g_Wg[(size_t)T_ * DM_];
__device__ __half g_Gm[(size_t)B_ * T_ * DM_];

// ---------------- helpers ----------------------------------------------------
__device__ __forceinline__ uint32_t pack_f16(float lo, float hi) {
    uint32_t u; asm("cvt.rn.f16x2.f32 %0, %1, %2;" : "=r"(u) : "f"(hi), "f"(lo)); return u;
}
__device__ __forceinline__ float2 h2f2(uint32_t u) {
    __half2 h = *reinterpret_cast<__half2*>(&u);
    return __half22float2(h);
}
__device__ __forceinline__ float ex2(float x) {
    float r; asm("ex2.approx.ftz.f32 %0, %1;" : "=f"(r) : "f"(x)); return r;
}
__device__ __forceinline__ void mma_f16(float* c, const uint32_t* a, const uint32_t* b) {
    asm volatile("mma.sync.aligned.m16n8k16.row.col.f32.f16.f16.f32 "
        "{%0,%1,%2,%3}, {%4,%5,%6,%7}, {%8,%9}, {%0,%1,%2,%3};\n"
        : "+f"(c[0]), "+f"(c[1]), "+f"(c[2]), "+f"(c[3])
        : "r"(a[0]), "r"(a[1]), "r"(a[2]), "r"(a[3]), "r"(b[0]), "r"(b[1]));
}
__device__ __forceinline__ uint32_t smem_u32(const void* p) {
    uint32_t a;
    asm("{ .reg .u64 t; cvta.to.shared.u64 t, %1; cvt.u32.u64 %0, t; }" : "=r"(a) : "l"(p));
    return a;
}
__device__ __forceinline__ void cp_async16(uint32_t dst, const void* src) {
    asm volatile("cp.async.cg.shared.global [%0], [%1], 16;"
                 :: "r"(dst), "l"(src) : "memory");
}

// ---------------- one-shot prolog: all fp32->fp16 conversions + Hf copy -----
#define N4_WQ  (D_ * D2_ / 4)            // 524288
#define N4_WV  (D_ * D_ / 4)             // 262144
#define N4_WG  (T_ * DM_ / 4)            // 131072
#define N4_GM  (B_ * T_ * DM_ / 4)       // 262144
#define N4_HF  (B_ * T_ * D_ / 4)        // 524288
#define SEG0   N4_WQ
#define SEG1   (SEG0 + N4_WQ)
#define SEG2   (SEG1 + N4_WV)
#define SEG3   (SEG2 + N4_WV)
#define SEG4   (SEG3 + N4_WG)
#define SEG5   (SEG4 + N4_GM)
#define SEG6   (SEG5 + N4_HF)

__global__ void prep_kernel(const float4* __restrict__ Wq, const float4* __restrict__ Wk,
                            const float4* __restrict__ Wv, const float4* __restrict__ Wo,
                            const float4* __restrict__ Wg, const float4* __restrict__ Gm,
                            const float4* __restrict__ Hf) {
    int gi = blockIdx.x * blockDim.x + threadIdx.x;
    if (gi >= SEG6) return;
    const float4* src; uint2* dst; int i;
    if (gi < SEG0)      { i = gi;        src = Wq; dst = (uint2*)g_Wq; }
    else if (gi < SEG1) { i = gi - SEG0; src = Wk; dst = (uint2*)g_Wk; }
    else if (gi < SEG2) { i = gi - SEG1; src = Wv; dst = (uint2*)g_Wv; }
    else if (gi < SEG3) { i = gi - SEG2; src = Wo; dst = (uint2*)g_Wo; }
    else if (gi < SEG4) { i = gi - SEG3; src = Wg; dst = (uint2*)g_Wg; }
    else if (gi < SEG5) { i = gi - SEG4; src = Gm; dst = (uint2*)g_Gm; }
    else {
        i = gi - SEG5;
        float4 v = Hf[i];
        int row = i / (D_ / 4), col4 = i % (D_ / 4);
        *reinterpret_cast<uint2*>(g_hcat + (size_t)row * D2_ + D_ + col4 * 4) =
            make_uint2(pack_f16(v.x, v.y), pack_f16(v.z, v.w));
        return;
    }
    float4 v = src[i];
    dst[i] = make_uint2(pack_f16(v.x, v.y), pack_f16(v.z, v.w));
}

// ---------------- hx transpose: Hx (B,D,T,1) -> g_hcat[:, 0:D] (fp16) -------
__global__ void transpose_hx_kernel(const float* __restrict__ Hx) {
    __shared__ float tile[32][33];
    int b  = blockIdx.z;
    int d0 = blockIdx.y * 32;
    int t0 = blockIdx.x * 32;
    #pragma unroll
    for (int yy = threadIdx.y; yy < 32; yy += 8)
        tile[yy][threadIdx.x] = Hx[((size_t)(b * D_ + d0 + yy)) * T_ + t0 + threadIdx.x];
    __syncthreads();
    #pragma unroll
    for (int yy = threadIdx.y; yy < 32; yy += 8)
        g_hcat[((size_t)(b * T_ + t0 + yy)) * D2_ + d0 + threadIdx.x] =
            __float2half(tile[threadIdx.x][yy]);
}

// ---------------- fp16 GEMM core (round-15 proven config) -------------------
// OUT: 0 = fp32*(oscale) to C, 1 = fp16 packed *(oscale) to C, 2 = fp16 to g_Vt.
#define PU    36
#define TILEU (128 * PU)
#define GEMM_SMEM (2 * 2 * TILEU * 4)             // 73728 B

template <int OUT>
__device__ __forceinline__ void gemm_core_f16(
    const uint32_t* __restrict__ A, int ldau,
    const uint32_t* __restrict__ W, int Kdim,
    const float* __restrict__ bias,
    void* __restrict__ Cv, int ldc,
    size_t mBase, int nBase, uint32_t* sm, float oscale)
{
    const uint32_t sm_base = smem_u32(sm);
    const int tid  = threadIdx.x;
    const int lane = tid & 31;
    const int warp = tid >> 5;
    const int g    = lane >> 2;
    const int tq   = lane & 3;
    const int wm   = warp & 1;
    const int wn   = warp >> 1;

    const uint32_t* Ap = A + mBase * ldau;
    const int ldwu = Kdim >> 1;
    const uint32_t* Wp = W + (size_t)nBase * ldwu;

    float acc[4][8][4];
    #pragma unroll
    for (int mt = 0; mt < 4; mt++)
        #pragma unroll
        for (int nt = 0; nt < 8; nt++)
            #pragma unroll
            for (int e = 0; e < 4; e++) acc[mt][nt][e] = 0.f;

    const int mrow = tid >> 3;
    const int kchk = (tid & 7) << 2;

    auto load_tile = [&](int s, int k0u) {
        uint32_t dA = sm_base + (uint32_t)(s * 2 * TILEU) * 4;
        uint32_t dB = dA + TILEU * 4;
        #pragma unroll
        for (int j = 0; j < 8; j++) {
            int m = mrow + 16 * j;
            cp_async16(dA + (uint32_t)(m * PU + kchk) * 4,
                       Ap + (size_t)m * ldau + k0u + kchk);
            cp_async16(dB + (uint32_t)(m * PU + kchk) * 4,
                       Wp + (size_t)m * ldwu + k0u + kchk);
        }
        asm volatile("cp.async.commit_group;" ::: "memory");
    };

    const int niter = Kdim >> 6;
    load_tile(0, 0);

    for (int it = 0; it < niter; it++) {
        if (it + 1 < niter) {
            load_tile((it + 1) & 1, (it + 1) << 5);
            asm volatile("cp.async.wait_group 1;" ::: "memory");
        } else {
            asm volatile("cp.async.wait_group 0;" ::: "memory");
        }
        __syncthreads();

        const uint32_t* sA = sm + (it & 1) * 2 * TILEU;
        const uint32_t* sB = sA + TILEU;

        #pragma unroll
        for (int s = 0; s < 4; s++) {
            const int k = 8 * s;
            uint32_t af[4][4], bf[8][2];
            #pragma unroll
            for (int mt = 0; mt < 4; mt++) {
                int m0 = wm * 64 + mt * 16 + g;
                af[mt][0] = sA[m0 * PU + k + tq];
                af[mt][1] = sA[(m0 + 8) * PU + k + tq];
                af[mt][2] = sA[m0 * PU + k + tq + 4];
                af[mt][3] = sA[(m0 + 8) * PU + k + tq + 4];
            }
            #pragma unroll
            for (int nt = 0; nt < 8; nt++) {
                int n0 = wn * 64 + nt * 8 + g;
                bf[nt][0] = sB[n0 * PU + k + tq];
                bf[nt][1] = sB[n0 * PU + k + tq + 4];
            }
            #pragma unroll
            for (int mt = 0; mt < 4; mt++)
                #pragma unroll
                for (int nt = 0; nt < 8; nt++)
                    mma_f16(acc[mt][nt], af[mt], bf[nt]);
        }
        __syncthreads();
    }

    #pragma unroll
    for (int nt = 0; nt < 8; nt++) {
        int col = nBase + wn * 64 + nt * 8 + 2 * tq;
        float2 bv = *reinterpret_cast<const float2*>(&bias[col]);
        #pragma unroll
        for (int mt = 0; mt < 4; mt++) {
            size_t row = mBase + wm * 64 + mt * 16 + g;
            float v00 = acc[mt][nt][0] + bv.x, v01 = acc[mt][nt][1] + bv.y;
            float v10 = acc[mt][nt][2] + bv.x, v11 = acc[mt][nt][3] + bv.y;
            if (OUT == 2) {
                int bb = (int)(row >> 11);
                int t  = (int)(row & 2047);
                __half* base = g_Vt + ((size_t)bb * D_ + col) * T_ + t;
                base[0]      = __float2half(v00);
                base[T_]     = __float2half(v01);
                base[8]      = __float2half(v10);
                base[T_ + 8] = __float2half(v11);
            } else if (OUT == 1) {
                uint32_t* Ch = reinterpret_cast<uint32_t*>(Cv);
                Ch[row * (ldc >> 1) + (col >> 1)] =
                    pack_f16(v00 * oscale, v01 * oscale);
                Ch[(row + 8) * (ldc >> 1) + (col >> 1)] =
                    pack_f16(v10 * oscale, v11 * oscale);
            } else {
                float* C = reinterpret_cast<float*>(Cv);
                *reinterpret_cast<float2*>(&C[row * ldc + col]) =
                    make_float2(v00 * oscale, v01 * oscale);
                *reinterpret_cast<float2*>(&C[(row + 8) * ldc + col]) =
                    make_float2(v10 * oscale, v11 * oscale);
            }
        }
    }
}

// ---- fused Q/K/V/bias projections (bias -> fp16, pre-scaled by log2e) ------
__global__ void __launch_bounds__(128) proj_fused_kernel(
    const float* __restrict__ bq, const float* __restrict__ bk,
    const float* __restrict__ bv, const float* __restrict__ bg)
{
    extern __shared__ uint32_t sm[];
    const int bx = blockIdx.x;
    const size_t mB = (size_t)blockIdx.y * 128;
    const uint32_t* hcat = reinterpret_cast<const uint32_t*>(g_hcat);
    if (bx < 8)
        gemm_core_f16<1>(hcat, D2_ / 2, (const uint32_t*)g_Wq, D2_, bq,
                         g_Q, D_, mB, bx * 128, sm, 1.f);
    else if (bx < 16)
        gemm_core_f16<1>(hcat, D2_ / 2, (const uint32_t*)g_Wk, D2_, bk,
                         g_K, D_, mB, (bx - 8) * 128, sm, 1.f);
    else if (bx < 24)
        gemm_core_f16<2>(hcat, D2_ / 2, (const uint32_t*)g_Wv, D_, bv,
                         nullptr, 0, mB, (bx - 16) * 128, sm, 1.f);
    else
        gemm_core_f16<1>((const uint32_t*)g_Gm, DM_ / 2, (const uint32_t*)g_Wg, DM_, bg,
                         g_bias, T_, mB, (bx - 24) * 128, sm, LOG2E);
}

__global__ void __launch_bounds__(128) out_proj_kernel(
    const float* __restrict__ bo, float* __restrict__ out)
{
    extern __shared__ uint32_t sm[];
    gemm_core_f16<0>((const uint32_t*)g_O, D_ / 2, (const uint32_t*)g_Wo, D_, bo,
                     out, D_, (size_t)blockIdx.y * 128, blockIdx.x * 128, sm, 1.f);
}

// ---------------- flash attention: fused S->P->PV, fp16 bias ----------------
// grid (h, q0, b): all 16 heads sharing a bias tile are adjacent block ids ->
// co-resident -> L2 reuse of the (head-independent) bias stream.
#define KLD  36
#define VLD  36
#define KWU  (64 * KLD)
#define VWU  (64 * VLD)
#define STGU (KWU + VWU)
#define ATTN_SMEM (2 * STGU * (int)sizeof(uint32_t))   // 36864 B

__global__ void __launch_bounds__(128, 1) attn_f16_kernel() {
    extern __shared__ uint32_t smu[];
    uint32_t* Qst = smu + STGU;       // Q staging in stage-1 buffer (clobbered)

    const int tid  = threadIdx.x;
    const int lane = tid & 31;
    const int warp = tid >> 5;
    const int g    = lane >> 2;
    const int tq   = lane & 3;
    const int h    = blockIdx.x;
    const int q0   = blockIdx.y * 128;
    const int b    = blockIdx.z;

    const uint32_t smb = smem_u32(smu);

    const uint32_t* __restrict__ Qg =
        reinterpret_cast<const uint32_t*>(g_Q) + ((size_t)b * T_ * D_ + (size_t)h * DK_) / 2;
    const uint32_t* __restrict__ Kg =
        reinterpret_cast<const uint32_t*>(g_K) + ((size_t)b * T_ * D_ + (size_t)h * DK_) / 2;
    const __half*   __restrict__ Vtg =
        g_Vt + ((size_t)b * D_ + (size_t)h * DK_) * T_;
    const uint32_t* __restrict__ Bgu =
        reinterpret_cast<const uint32_t*>(g_bias) + ((size_t)b * T_ + q0) * (T_ / 2);

    const int ldq = D_ / 2;
    const int ldb = T_ / 2;
    const float SC = 0.125f * LOG2E;

    auto load_kv = [&](int st, int k0) {
        uint32_t dK = smb + (uint32_t)(st * STGU) * 4;
        uint32_t dV = dK + KWU * 4;
        #pragma unroll
        for (int j = 0; j < 4; j++) {
            int i = tid + 128 * j;
            int r = i >> 3, c = i & 7;
            cp_async16(dK + (uint32_t)(r * KLD + 4 * c) * 4,
                       Kg + (size_t)(k0 + r) * ldq + 4 * c);
        }
        #pragma unroll
        for (int j = 0; j < 4; j++) {
            int i = tid + 128 * j;
            int r = i >> 3, c = i & 7;
            cp_async16(dV + (uint32_t)(r * VLD + 4 * c) * 4,
                       Vtg + (size_t)r * T_ + k0 + 8 * c);
        }
        asm volatile("cp.async.commit_group;" ::: "memory");
    };

    load_kv(0, 0);

    #pragma unroll
    for (int i = tid; i < 128 * 8; i += 128) {
        int r = i >> 3, c4 = (i & 7) << 2;
        uint4 v = *reinterpret_cast<const uint4*>(&Qg[(size_t)(q0 + r) * ldq + c4]);
        *reinterpret_cast<uint4*>(&Qst[r * 36 + c4]) = v;
    }
    __syncthreads();

    uint32_t qa0[4][4], qa1[4][4];
    {
        const uint32_t* Q0 = Qst + (warp * 32 + g) * 36;
        const uint32_t* Q1 = Qst + (warp * 32 + 16 + g) * 36;
        #pragma unroll
        for (int s = 0; s < 4; s++) {
            qa0[s][0] = Q0[8 * s + tq];
            qa0[s][1] = Q0[8 * 36 + 8 * s + tq];
            qa0[s][2] = Q0[8 * s + tq + 4];
            qa0[s][3] = Q0[8 * 36 + 8 * s + tq + 4];
            qa1[s][0] = Q1[8 * s + tq];
            qa1[s][1] = Q1[8 * 36 + 8 * s + tq];
            qa1[s][2] = Q1[8 * s + tq + 4];
            qa1[s][3] = Q1[8 * 36 + 8 * s + tq + 4];
        }
    }
    __syncthreads();

    float o0[8][4], o1[8][4];
    #pragma unroll
    for (int nt = 0; nt < 8; nt++)
        #pragma unroll
        for (int e = 0; e < 4; e++) { o0[nt][e] = 0.f; o1[nt][e] = 0.f; }
    float rs[4] = {0.f, 0.f, 0.f, 0.f};

    const int niter = T_ / 64;

    for (int it = 0; it < niter; it++) {
        const int k0 = it * 64;
        if (it + 1 < niter) {
            load_kv((it + 1) & 1, k0 + 64);
            asm volatile("cp.async.wait_group 1;" ::: "memory");
        } else {
            asm volatile("cp.async.wait_group 0;" ::: "memory");
        }
        __syncthreads();

        const uint32_t* sK  = smu + (it & 1) * STGU;
        const uint32_t* sVt = sK + KWU;
        const uint32_t* B0  = Bgu + (size_t)(warp * 32 + g) * ldb + k0 / 2;

        #pragma unroll
        for (int ntp = 0; ntp < 4; ntp++) {
            const int ntA = 2 * ntp, ntB = 2 * ntp + 1;
            const int cuA = ntA * 4 + tq, cuB = ntB * 4 + tq;

            float2 bA00 = h2f2(B0[cuA]);
            float2 bA01 = h2f2(B0[8  * ldb + cuA]);
            float2 bA10 = h2f2(B0[16 * ldb + cuA]);
            float2 bA11 = h2f2(B0[24 * ldb + cuA]);
            float2 bB00 = h2f2(B0[cuB]);
            float2 bB01 = h2f2(B0[8  * ldb + cuB]);
            float2 bB10 = h2f2(B0[16 * ldb + cuB]);
            float2 bB11 = h2f2(B0[24 * ldb + cuB]);

            float sA0[4] = {0.f,0.f,0.f,0.f}, sA1[4] = {0.f,0.f,0.f,0.f};
            float sB0[4] = {0.f,0.f,0.f,0.f}, sB1[4] = {0.f,0.f,0.f,0.f};
            #pragma unroll
            for (int s = 0; s < 4; s++) {
                const uint32_t* KrA = sK + (ntA * 8 + g) * KLD + 8 * s + tq;
                const uint32_t* KrB = sK + (ntB * 8 + g) * KLD + 8 * s + tq;
                uint32_t bbA[2] = { KrA[0], KrA[4] };
                uint32_t bbB[2] = { KrB[0], KrB[4] };
                mma_f16(sA0, qa0[s], bbA);
                mma_f16(sA1, qa1[s], bbA);
                mma_f16(sB0, qa0[s], bbB);
                mma_f16(sB1, qa1[s], bbB);
            }

            float pA00 = ex2(fmaf(sA0[0], SC, bA00.x));
            float pA01 = ex2(fmaf(sA0[1], SC, bA00.y));
            float pA02 = ex2(fmaf(sA0[2], SC, bA01.x));
            float pA03 = ex2(fmaf(sA0[3], SC, bA01.y));
            float pA10 = ex2(fmaf(sA1[0], SC, bA10.x));
            float pA11 = ex2(fmaf(sA1[1], SC, bA10.y));
            float pA12 = ex2(fmaf(sA1[2], SC, bA11.x));
            float pA13 = ex2(fmaf(sA1[3], SC, bA11.y));
            float pB00 = ex2(fmaf(sB0[0], SC, bB00.x));
            float pB01 = ex2(fmaf(sB0[1], SC, bB00.y));
            float pB02 = ex2(fmaf(sB0[2], SC, bB01.x));
            float pB03 = ex2(fmaf(sB0[3], SC, bB01.y));
            float pB10 = ex2(fmaf(sB1[0], SC, bB10.x));
            float pB11 = ex2(fmaf(sB1[1], SC, bB10.y));
            float pB12 = ex2(fmaf(sB1[2], SC, bB11.x));
            float pB13 = ex2(fmaf(sB1[3], SC, bB11.y));

            rs[0] += pA00 + pA01 + pB00 + pB01;
            rs[1] += pA02 + pA03 + pB02 + pB03;
            rs[2] += pA10 + pA11 + pB10 + pB11;
            rs[3] += pA12 + pA13 + pB12 + pB13;

            uint32_t pa0[4], pa1[4];
            pa0[0] = pack_f16(pA00, pA01);
            pa0[1] = pack_f16(pA02, pA03);
            pa0[2] = pack_f16(pB00, pB01);
            pa0[3] = pack_f16(pB02, pB03);
            pa1[0] = pack_f16(pA10, pA11);
            pa1[1] = pack_f16(pA12, pA13);
            pa1[2] = pack_f16(pB10, pB11);
            pa1[3] = pack_f16(pB12, pB13);

            #pragma unroll
            for (int nt = 0; nt < 8; nt++) {
                uint32_t bb[2];
                bb[0] = sVt[(nt * 8 + g) * VLD + 8 * ntp + tq];
                bb[1] = sVt[(nt * 8 + g) * VLD + 8 * ntp + tq + 4];
                mma_f16(o0[nt], pa0, bb);
                mma_f16(o1[nt], pa1, bb);
            }
        }
        __syncthreads();
    }

    #pragma unroll
    for (int e = 0; e < 4; e++) {
        rs[e] += __shfl_xor_sync(0xffffffffu, rs[e], 1);
        rs[e] += __shfl_xor_sync(0xffffffffu, rs[e], 2);
    }
    float inv0 = 1.0f / rs[0], inv1 = 1.0f / rs[1];
    float inv2 = 1.0f / rs[2], inv3 = 1.0f / rs[3];

    uint32_t* Og = reinterpret_cast<uint32_t*>(g_O) +
                   ((size_t)b * T_ * D_ + (size_t)h * DK_) / 2;
    size_t r0 = (size_t)q0 + warp * 32 + g;
    const int ldo = D_ / 2;
    #pragma unroll
    for (int nt = 0; nt < 8; nt++) {
        int cu = nt * 4 + tq;
        Og[r0 * ldo + cu]        = pack_f16(o0[nt][0] * inv0, o0[nt][1] * inv0);
        Og[(r0 + 8) * ldo + cu]  = pack_f16(o0[nt][2] * inv1, o0[nt][3] * inv1);
        Og[(r0 + 16) * ldo + cu] = pack_f16(o1[nt][0] * inv2, o1[nt][1] * inv2);
        Og[(r0 + 24) * ldo + cu] = pack_f16(o1[nt][2] * inv3, o1[nt][3] * inv3);
    }
}

// ---------------- launch ----------------------------------------------------
extern "C" void kernel_launch(void* const* d_in, const int* in_sizes, int n_in,
                              void* d_out, int out_size) {
    const float* Hx = (const float*)d_in[0];
    const float* Hf = (const float*)d_in[1];
    const float* Gm = (const float*)d_in[2];
    const float* Wg = (const float*)d_in[3];
    const float* bg = (const float*)d_in[4];
    const float* Wq = (const float*)d_in[5];
    const float* bq = (const float*)d_in[6];
    const float* Wk = (const float*)d_in[7];
    const float* bk = (const float*)d_in[8];
    const float* Wv = (const float*)d_in[9];
    const float* bv = (const float*)d_in[10];
    const float* Wo = (const float*)d_in[11];
    const float* bo = (const float*)d_in[12];
    float* out = (float*)d_out;

    cudaFuncSetAttribute(proj_fused_kernel,
                         cudaFuncAttributeMaxDynamicSharedMemorySize, GEMM_SMEM);
    cudaFuncSetAttribute(out_proj_kernel,
                         cudaFuncAttributeMaxDynamicSharedMemorySize, GEMM_SMEM);
    cudaFuncSetAttribute(attn_f16_kernel,
                         cudaFuncAttributeMaxDynamicSharedMemorySize, ATTN_SMEM);

    // 0) one-shot prolog: all weight/Gm conversions + Hf copy
    prep_kernel<<<(SEG6 + 255) / 256, 256>>>(
        (const float4*)Wq, (const float4*)Wk, (const float4*)Wv,
        (const float4*)Wo, (const float4*)Wg, (const float4*)Gm,
        (const float4*)Hf);

    // 1) hx transpose into hcat[:, 0:D]
    transpose_hx_kernel<<<dim3(T_ / 32, D_ / 32, B_), dim3(32, 8)>>>(Hx);

    // 2) all projections in ONE launch (bias -> fp16 * log2e)
    proj_fused_kernel<<<dim3(40, 32), 128, GEMM_SMEM>>>(bq, bk, bv, bg);

    // 3) attention (grid: heads adjacent for bias L2 reuse)
    attn_f16_kernel<<<dim3(H_, T_ / 128, B_), 128, ATTN_SMEM>>>();

    // 4) output projection (fp16 in, fp32 out)
    out_proj_kernel<<<dim3(D_ / 128, 32), 128, GEMM_SMEM>>>(bo, out);
}